// round 9
// baseline (speedup 1.0000x reference)
#include <cuda_runtime.h>
#include <cuda_bf16.h>
#include <cstdint>

#define N_TOT 65536
#define GRP   512
#define PER   128
#define DIM   256
#define SEQL  1534
#define HID   512
#define KCH   32

typedef __nv_bfloat16 bf16;

// ---------------- scratch (device globals; no allocation allowed) ----------
__device__ bf16  g_hh  [N_TOT * DIM];
__device__ bf16  g_hl  [N_TOT * DIM];
__device__ float g_HAts[GRP * DIM];
__device__ float g_seqf[1536 * DIM];
__device__ bf16  g_seqh[1536 * DIM];
__device__ bf16  g_seql[1536 * DIM];
__device__ bf16  g_x1h [1536 * 512];
__device__ bf16  g_x1l [1536 * 512];
__device__ float g_x2f [1536 * 512];
__device__ bf16  g_x2h [1536 * 512];
__device__ bf16  g_x2l [1536 * 512];
__device__ bf16  g_wah [DIM * DIM];
__device__ bf16  g_wal [DIM * DIM];
__device__ bf16  g_wc0h[3 * 256 * 256];
__device__ bf16  g_wc0l[3 * 256 * 256];
__device__ bf16  g_wc1h[3 * 512 * 256];
__device__ bf16  g_wc1l[3 * 512 * 256];
__device__ bf16  g_wc2h[3 * 512 * 512];
__device__ bf16  g_wc2l[3 * 512 * 512];
__device__ bf16  g_wc3h[3 * 256 * 512];
__device__ bf16  g_wc3l[3 * 256 * 512];
__device__ bf16  g_wd1h[512 * 256];
__device__ bf16  g_wd1l[512 * 256];
__device__ bf16  g_wd3h[256 * 512];
__device__ bf16  g_wd3l[256 * 512];
__device__ bf16  g_wp1th[512 * 768];
__device__ bf16  g_wp1tl[512 * 768];
__device__ bf16  g_wp1bh[512 * 256];
__device__ bf16  g_wp1bl[512 * 256];
__device__ bf16  g_sHSh[GRP * 768];
__device__ bf16  g_sHSl[GRP * 768];
__device__ float g_GT  [GRP * 512];

// ---------------- low-level helpers -----------------------------------------
__device__ __forceinline__ uint32_t smem_u32(const void* p) {
    uint32_t a;
    asm("{ .reg .u64 t; cvta.to.shared.u64 t, %1; cvt.u32.u64 %0, t; }"
        : "=r"(a) : "l"(p));
    return a;
}
static __device__ __forceinline__ uint32_t SWZ(uint32_t off) {
    return off ^ ((off >> 3) & 0x70);
}
__device__ __forceinline__ void mma_bf16(float* c, const uint32_t* a, const uint32_t* b) {
    asm volatile(
        "mma.sync.aligned.m16n8k16.row.col.f32.bf16.bf16.f32 "
        "{%0,%1,%2,%3}, {%4,%5,%6,%7}, {%8,%9}, {%0,%1,%2,%3};\n"
        : "+f"(c[0]), "+f"(c[1]), "+f"(c[2]), "+f"(c[3])
        : "r"(a[0]), "r"(a[1]), "r"(a[2]), "r"(a[3]), "r"(b[0]), "r"(b[1]));
}
__device__ __forceinline__ void ldm_x4(uint32_t* r, uint32_t a) {
    asm volatile("ldmatrix.sync.aligned.m8n8.x4.shared.b16 {%0,%1,%2,%3}, [%4];"
        : "=r"(r[0]), "=r"(r[1]), "=r"(r[2]), "=r"(r[3]) : "r"(a));
}
#define CP16(dst, src, pred) do {                                              \
    int _sz = (pred) ? 16 : 0;                                                 \
    asm volatile("cp.async.cg.shared.global [%0], [%1], 16, %2;"               \
        :: "r"(dst), "l"(src), "r"(_sz) : "memory"); } while (0)
#define CP_COMMIT() asm volatile("cp.async.commit_group;" ::: "memory")
#define CP_WAIT1()  asm volatile("cp.async.wait_group 1;" ::: "memory")
#define CP_WAIT0()  asm volatile("cp.async.wait_group 0;" ::: "memory")

// ---------------- split helpers ---------------------------------------------
__device__ __forceinline__ void split2(float v, bf16& h, bf16& l) {
    h = __float2bfloat16(v);
    l = __float2bfloat16(v - __bfloat162float(h));
}
__device__ __forceinline__ void d_tsplit(const float* w, bf16* h, bf16* l,
                                         int K, int N, int i)
{
    if (i < K * N) {
        int k = i / N, n = i % N;
        bf16 a, b; split2(w[i], a, b);
        h[(size_t)n * K + k] = a;
        l[(size_t)n * K + k] = b;
    }
}
__device__ __forceinline__ void d_conv(const float* w, bf16* h, bf16* l,
                                       int Cout, int Cin, int i)
{
    if (i < Cout * Cin * 3) {
        int j  = i % 3;
        int ci = (i / 3) % Cin;
        int co = i / (3 * Cin);
        bf16 a, b; split2(w[i], a, b);
        size_t d = ((size_t)j * Cout + co) * Cin + ci;
        h[d] = a; l[d] = b;
    }
}
__device__ __forceinline__ void d_arr(const float* w, bf16* h, bf16* l, int n, int i)
{
    if (i < n) { bf16 a, b; split2(w[i], a, b); h[i] = a; l[i] = b; }
}

__global__ void split_weights(
    const float* Wa, const float* Wc0, const float* Wc1, const float* Wc2,
    const float* Wc3, const float* Wd1, const float* Wd3, const float* Wp1,
    bf16* wah, bf16* wal, bf16* wc0h, bf16* wc0l, bf16* wc1h, bf16* wc1l,
    bf16* wc2h, bf16* wc2l, bf16* wc3h, bf16* wc3l, bf16* wd1h, bf16* wd1l,
    bf16* wd3h, bf16* wd3l, bf16* wp1th, bf16* wp1tl, bf16* wp1bh, bf16* wp1bl)
{
    int b = blockIdx.x, t = threadIdx.x;
    if (b < 256)        { d_tsplit(Wa, wah, wal, 256, 256, b * 256 + t); return; }
    b -= 256;
    if (b < 768)        { d_conv(Wc0, wc0h, wc0l, 256, 256, b * 256 + t); return; }
    b -= 768;
    if (b < 1536)       { d_conv(Wc1, wc1h, wc1l, 512, 256, b * 256 + t); return; }
    b -= 1536;
    if (b < 3072)       { d_conv(Wc2, wc2h, wc2l, 512, 512, b * 256 + t); return; }
    b -= 3072;
    if (b < 1536)       { d_conv(Wc3, wc3h, wc3l, 256, 512, b * 256 + t); return; }
    b -= 1536;
    if (b < 512)        { d_arr(Wd1, wd1h, wd1l, 512 * 256, b * 256 + t); return; }
    b -= 512;
    if (b < 512)        { d_arr(Wd3, wd3h, wd3l, 256 * 512, b * 256 + t); return; }
    b -= 512;
    if (b < 1536)       { d_tsplit(Wp1, wp1th, wp1tl, 768, 512, b * 256 + t); return; }
    b -= 1536;
    if (b < 512)        { d_tsplit(Wp1 + 768 * 512, wp1bh, wp1bl, 256, 512, b * 256 + t); }
}
#define SPLITW_BLOCKS (256 + 768 + 1536 + 3072 + 1536 + 512 + 512 + 1536 + 512)

// ---------------- warp compute for one k32 chunk -----------------------------
template<int NBT>
__device__ __forceinline__ void compute_chunk_t(uint32_t Ab, uint32_t Bb, int aoff,
                                                int wm, int wn, int lane,
                                                float acc[2][NBT][4])
{
    int l7 = lane & 7;
    int b3 = (lane >> 3) & 1;
    int b4 = (lane >> 4) & 1;
    #pragma unroll
    for (int ks = 0; ks < 2; ks++) {
        int colb = ks * 32;
        uint32_t bh[NBT][2], bl[NBT][2];
        #pragma unroll
        for (int pp = 0; pp < NBT / 2; pp++) {
            int nrow = wn + pp * 16 + b4 * 8 + l7;
            uint32_t off = nrow * 128 + colb + b3 * 16;
            uint32_t rh[4], rl[4];
            ldm_x4(rh, Bb + SWZ(off));
            ldm_x4(rl, Bb + SWZ(off + 64));
            bh[pp * 2 + 0][0] = rh[0]; bh[pp * 2 + 0][1] = rh[1];
            bh[pp * 2 + 1][0] = rh[2]; bh[pp * 2 + 1][1] = rh[3];
            bl[pp * 2 + 0][0] = rl[0]; bl[pp * 2 + 0][1] = rl[1];
            bl[pp * 2 + 1][0] = rl[2]; bl[pp * 2 + 1][1] = rl[3];
        }
        #pragma unroll
        for (int mt = 0; mt < 2; mt++) {
            int arow = aoff + wm + mt * 16 + b3 * 8 + l7;
            uint32_t off = arow * 128 + colb + b4 * 16;
            uint32_t ah[4], al[4];
            ldm_x4(ah, Ab + SWZ(off));
            ldm_x4(al, Ab + SWZ(off + 64));
            #pragma unroll
            for (int bt = 0; bt < NBT; bt++) {
                mma_bf16(acc[mt][bt], ah, bh[bt]);
                mma_bf16(acc[mt][bt], ah, bl[bt]);
                mma_bf16(acc[mt][bt], al, bh[bt]);
            }
        }
    }
}

// ---------------- fused hats + segment max + state_seq ----------------------
// one block per group g: computes relu(NEs[g*128..+128] @ Wa^T + ba) for all
// 256 cols, writes hi/lo, group col-max -> HAts + seq row 3g+1,
// act row -> seq row 3g+2, nodes -> seq row 3g (or row 1533 for g=511).
// A read directly as fp32 (LDG->regs->split->STS).
#define FH_STAGE 49152u
#define FH_DYN   (2 * 49152 + 1024)
__global__ __launch_bounds__(512, 1)
void fused_hats(const float* __restrict__ NEs,
                const bf16* __restrict__ Wgh, const bf16* __restrict__ Wgl,
                const float* __restrict__ bias,
                const float* __restrict__ nodes, const int* __restrict__ act,
                bf16* __restrict__ Ch, bf16* __restrict__ Cl,
                float* __restrict__ HAts, float* __restrict__ seqf,
                bf16* __restrict__ seqh, bf16* __restrict__ seql)
{
    extern __shared__ char dyn[];
    __shared__ float smax[4][256];
    uint32_t sbase = (smem_u32(dyn) + 1023u) & ~1023u;
    int g = blockIdx.x;
    int tid = threadIdx.x, lane = tid & 31, w = tid >> 5;
    int wm = (w & 3) * 32, wn = (w >> 2) * 64;
    const int nch = 8;

    float4 ar[2];
    auto load_A = [&](int c) {
        int k0 = c * KCH;
        #pragma unroll
        for (int t = 0; t < 2; t++) {
            int idx = tid + t * 512;
            int row = idx >> 3, seg = idx & 7;
            ar[t] = *(const float4*)(NEs + (size_t)(g * 128 + row) * 256 + k0 + seg * 4);
        }
    };
    auto sts_A = [&](int s) {
        uint32_t Ab = sbase + (uint32_t)s * FH_STAGE;
        #pragma unroll
        for (int t = 0; t < 2; t++) {
            int idx = tid + t * 512;
            int row = idx >> 3, seg = idx & 7;
            float4 f = ar[t];
            bf16 h0, l0, h1, l1, h2, l2, h3, l3;
            split2(f.x, h0, l0); split2(f.y, h1, l1);
            split2(f.z, h2, l2); split2(f.w, h3, l3);
            __nv_bfloat162 hp0 = {h0, h1}, hp1 = {h2, h3};
            __nv_bfloat162 lp0 = {l0, l1}, lp1 = {l2, l3};
            uint32_t hofs = SWZ((uint32_t)(row * 128 + seg * 8));
            uint32_t lofs = SWZ((uint32_t)(row * 128 + 64 + seg * 8));
            asm volatile("st.shared.v2.b32 [%0], {%1,%2};" :: "r"(Ab + hofs),
                "r"(*(uint32_t*)&hp0), "r"(*(uint32_t*)&hp1) : "memory");
            asm volatile("st.shared.v2.b32 [%0], {%1,%2};" :: "r"(Ab + lofs),
                "r"(*(uint32_t*)&lp0), "r"(*(uint32_t*)&lp1) : "memory");
        }
    };
    auto load_B = [&](int c, int s) {
        int k0 = c * KCH;
        uint32_t Bb = sbase + (uint32_t)s * FH_STAGE + 16384u;
        #pragma unroll
        for (int t = 0; t < 4; t++) {
            int idx = tid + t * 512;
            int row = idx >> 3, sub = idx & 7, half = sub >> 2, q = sub & 3;
            const bf16* src = (half ? Wgl : Wgh) + (size_t)row * 256 + k0 + q * 8;
            CP16(Bb + SWZ(row * 128 + half * 64 + q * 16), src, 1);
        }
    };

    float accA[2][4][4] = {}, accB[2][4][4] = {};
    load_A(0);
    load_B(0, 0); CP_COMMIT();
    load_B(1, 1); CP_COMMIT();
    for (int c = 0; c < nch; c++) {
        if (c + 1 < nch) { CP_WAIT1(); } else { CP_WAIT0(); }
        sts_A(c & 1);
        __syncthreads();
        if (c + 1 < nch) load_A(c + 1);
        uint32_t Ab = sbase + (uint32_t)(c & 1) * FH_STAGE;
        uint32_t Bb = Ab + 16384u;
        compute_chunk_t<4>(Ab, Bb, 0, wm, wn, lane, accA);
        compute_chunk_t<4>(Ab, Bb, 0, wm, wn + 32, lane, accB);
        __syncthreads();
        if (c + 2 < nch) { load_B(c + 2, c & 1); CP_COMMIT(); }
    }

    // epilogue: write hats hi/lo, col-max, act row
    float cmax[16];
    #pragma unroll
    for (int i = 0; i < 16; i++) cmax[i] = 0.f;   // relu outputs >= 0
    int ra = (g < GRP - 1) ? act[g] : -1;

    auto epi = [&](float (&acc)[2][4][4], int hb) {
        #pragma unroll
        for (int mt = 0; mt < 2; mt++) {
            #pragma unroll
            for (int ih = 0; ih < 2; ih++) {
                int r = wm + mt * 16 + ih * 8 + (lane >> 2);
                #pragma unroll
                for (int bt = 0; bt < 4; bt++) {
                    int cc = wn + hb + bt * 8 + (lane & 3) * 2;
                    float v0 = fmaxf(acc[mt][bt][ih * 2 + 0] + bias[cc], 0.f);
                    float v1 = fmaxf(acc[mt][bt][ih * 2 + 1] + bias[cc + 1], 0.f);
                    size_t idx = (size_t)(g * 128 + r) * 256 + cc;
                    bf16 h0, l0, h1, l1;
                    split2(v0, h0, l0); split2(v1, h1, l1);
                    __nv_bfloat162 hp = {h0, h1}, lp = {l0, l1};
                    *(__nv_bfloat162*)(Ch + idx) = hp;
                    *(__nv_bfloat162*)(Cl + idx) = lp;
                    int ci = (hb >> 2) + bt * 2;   // hb 0->0, 32->8
                    cmax[ci]     = fmaxf(cmax[ci], v0);
                    cmax[ci + 1] = fmaxf(cmax[ci + 1], v1);
                    if (r == ra) {
                        size_t sid = (size_t)(3 * g + 2) * 256 + cc;
                        *(float2*)(seqf + sid) = make_float2(v0, v1);
                        *(__nv_bfloat162*)(seqh + sid) = hp;
                        *(__nv_bfloat162*)(seql + sid) = lp;
                    }
                }
            }
        }
    };
    epi(accA, 0);
    epi(accB, 32);

    #pragma unroll
    for (int i = 0; i < 16; i++) {
        float m = cmax[i];
        m = fmaxf(m, __shfl_xor_sync(0xffffffffu, m, 4));
        m = fmaxf(m, __shfl_xor_sync(0xffffffffu, m, 8));
        m = fmaxf(m, __shfl_xor_sync(0xffffffffu, m, 16));
        cmax[i] = m;
    }
    if ((lane >> 2) == 0) {
        #pragma unroll
        for (int hb = 0; hb < 2; hb++)
            #pragma unroll
            for (int bt = 0; bt < 4; bt++) {
                int cc = wn + hb * 32 + bt * 8 + lane * 2;
                smax[w & 3][cc]     = cmax[hb * 8 + bt * 2];
                smax[w & 3][cc + 1] = cmax[hb * 8 + bt * 2 + 1];
            }
    }
    __syncthreads();
    if (tid < 256) {
        int cc = tid;
        float m = fmaxf(fmaxf(smax[0][cc], smax[1][cc]),
                        fmaxf(smax[2][cc], smax[3][cc]));
        HAts[g * 256 + cc] = m;
        bf16 a, b;
        if (g < GRP - 1) {
            size_t sid = (size_t)(3 * g + 1) * 256 + cc;
            seqf[sid] = m;
            split2(m, a, b); seqh[sid] = a; seql[sid] = b;
            float nv = nodes[g * 256 + cc];
            sid = (size_t)(3 * g) * 256 + cc;
            seqf[sid] = nv;
            split2(nv, a, b); seqh[sid] = a; seql[sid] = b;
        } else {
            float nv = nodes[g * 256 + cc];
            size_t sid = (size_t)(SEQL - 1) * 256 + cc;
            seqf[sid] = nv;
            split2(nv, a, b); seqh[sid] = a; seql[sid] = b;
        }
    }
}

// ---------------- TCN with halo (dynamic stage size) -------------------------
template<int DUAL>
__global__ __launch_bounds__(128, 3)
void tcn64(const bf16* __restrict__ Agh, const bf16* __restrict__ Agl,
           const bf16* __restrict__ Wgh, const bf16* __restrict__ Wgl,
           const bf16* __restrict__ Wdh, const bf16* __restrict__ Wdl,
           const float* __restrict__ bias, const float* __restrict__ Rf,
           float* __restrict__ Cf, bf16* __restrict__ Ch, bf16* __restrict__ Cl,
           int Mv, int N, int K, int npass, int dil, int doRelu)
{
    extern __shared__ char dyn[];
    uint32_t sbase = (smem_u32(dyn) + 1023u) & ~1023u;
    int tid = threadIdx.x, lane = tid & 31, w = tid >> 5;
    int wm = (w & 1) * 32, wn = (w >> 1) * 32;
    int row0 = blockIdx.y * 64, col0 = blockIdx.x * 64;
    int halo = (npass >= 3) ? 2 * dil : 0;
    int nrows = 64 + halo;
    uint32_t Abytes = (uint32_t)nrows * 128u;
    uint32_t stage = (Abytes + (uint32_t)npass * 8192u + 1023u) & ~1023u;
    int nch = K / KCH;

    auto load_stage = [&](int c, int s) {
        int k0 = c * KCH;
        uint32_t Ab = sbase + (uint32_t)s * stage;
        for (int idx = tid; idx < nrows * 8; idx += 128) {
            int row = idx >> 3, sub = idx & 7, half = sub >> 2, q = sub & 3;
            int ga = row0 - halo + row;
            const bf16* src = (half ? Agl : Agh)
                              + (size_t)(ga < 0 ? 0 : ga) * K + k0 + q * 8;
            CP16(Ab + SWZ(row * 128 + half * 64 + q * 16), src, ga >= 0);
        }
        for (int p = 0; p < npass; p++) {
            const bf16* Ph = (p < 3) ? Wgh + (size_t)p * N * K : Wdh;
            const bf16* Pl = (p < 3) ? Wgl + (size_t)p * N * K : Wdl;
            uint32_t Bb = Ab + Abytes + (uint32_t)p * 8192u;
            #pragma unroll
            for (int t = 0; t < 4; t++) {
                int idx = tid + t * 128;
                int row = idx >> 3, sub = idx & 7, half = sub >> 2, q = sub & 3;
                const bf16* src = (half ? Pl : Ph) + (size_t)(col0 + row) * K + k0 + q * 8;
                CP16(Bb + SWZ(row * 128 + half * 64 + q * 16), src, 1);
            }
        }
    };

    float acc[2][4][4] = {};
    float accR[DUAL ? 2 : 1][DUAL ? 4 : 1][DUAL ? 4 : 1] = {};
    load_stage(0, 0); CP_COMMIT();
    if (nch > 1) { load_stage(1, 1); CP_COMMIT(); }
    for (int c = 0; c < nch; c++) {
        if (c + 1 < nch) { CP_WAIT1(); } else { CP_WAIT0(); }
        __syncthreads();
        uint32_t Ab = sbase + (uint32_t)(c & 1) * stage;
        for (int p = 0; p < npass; p++) {
            int aoff = (p < 3) ? p * dil : 2 * dil;
            uint32_t Bb = Ab + Abytes + (uint32_t)p * 8192u;
            if (DUAL && p == 3)
                compute_chunk_t<4>(Ab, Bb, aoff, wm, wn, lane, (float (*)[4][4])accR);
            else
                compute_chunk_t<4>(Ab, Bb, aoff, wm, wn, lane, acc);
        }
        __syncthreads();
        if (c + 2 < nch) { load_stage(c + 2, c & 1); CP_COMMIT(); }
    }

    #pragma unroll
    for (int mt = 0; mt < 2; mt++) {
        #pragma unroll
        for (int ih = 0; ih < 2; ih++) {
            int rr = row0 + wm + mt * 16 + ih * 8 + (lane >> 2);
            if (rr >= Mv) continue;
            #pragma unroll
            for (int bt = 0; bt < 4; bt++) {
                int cc = col0 + wn + bt * 8 + (lane & 3) * 2;
                size_t idx = (size_t)rr * N + cc;
                float v0 = acc[mt][bt][ih * 2 + 0] + bias[cc];
                float v1 = acc[mt][bt][ih * 2 + 1] + bias[cc + 1];
                if (doRelu) { v0 = fmaxf(v0, 0.f); v1 = fmaxf(v1, 0.f); }
                if (DUAL) {
                    v0 = fmaxf(v0 + accR[mt][bt][ih * 2 + 0], 0.f);
                    v1 = fmaxf(v1 + accR[mt][bt][ih * 2 + 1], 0.f);
                } else if (Rf) {
                    float2 rv = *(const float2*)(Rf + idx);
                    v0 = fmaxf(v0 + rv.x, 0.f);
                    v1 = fmaxf(v1 + rv.y, 0.f);
                }
                if (Cf) *(float2*)(Cf + idx) = make_float2(v0, v1);
                if (Ch) {
                    bf16 h0, l0, h1, l1;
                    split2(v0, h0, l0); split2(v1, h1, l1);
                    __nv_bfloat162 hp = {h0, h1}, lp = {l0, l1};
                    *(__nv_bfloat162*)(Ch + idx) = hp;
                    *(__nv_bfloat162*)(Cl + idx) = lp;
                }
            }
        }
    }
}

static int tcn_dyn(int npass, int dil) {
    int halo = (npass >= 3) ? 2 * dil : 0;
    unsigned Abytes = (unsigned)(64 + halo) * 128u;
    unsigned stage = (Abytes + (unsigned)npass * 8192u + 1023u) & ~1023u;
    return (int)(2 * stage + 1024);
}

// ---------------- fused final: out = relu(hats@Wp1bot + GT[g]) @ Wp2 + bp2 --
#define FIN_STAGE 24576u
#define FIN_DYN   (2 * 24576 + 1024)
__global__ __launch_bounds__(256, 2)
void final_mma(const bf16* __restrict__ Hh, const bf16* __restrict__ Hl,
               const bf16* __restrict__ Bgh, const bf16* __restrict__ Bgl,
               const float* __restrict__ GT, const float* __restrict__ W2,
               const float* __restrict__ bp2, float* __restrict__ out)
{
    extern __shared__ char dyn[];
    __shared__ float sGT[512], sW2[512], sred[128][2];
    uint32_t sbase = (smem_u32(dyn) + 1023u) & ~1023u;
    int g = blockIdx.x;
    int tid = threadIdx.x, lane = tid & 31, w = tid >> 5;
    int wm = (w & 3) * 32, wn = (w >> 2) * 32;

    for (int i = tid; i < 512; i += 256) {
        sGT[i] = GT[(size_t)g * 512 + i];
        sW2[i] = W2[i];
    }

    const bf16* Ah = Hh + (size_t)g * PER * DIM;
    const bf16* Al = Hl + (size_t)g * PER * DIM;

    auto load_stage = [&](int c, int s) {
        int nt = c >> 3;
        int k0 = (c & 7) * KCH;
        uint32_t Ab = sbase + (uint32_t)s * FIN_STAGE;
        uint32_t Bb = Ab + 16384u;
        #pragma unroll
        for (int t = 0; t < 4; t++) {
            int idx = tid + t * 256;
            int row = idx >> 3, sub = idx & 7, half = sub >> 2, q = sub & 3;
            const bf16* src = (half ? Al : Ah) + (size_t)row * DIM + k0 + q * 8;
            CP16(Ab + SWZ(row * 128 + half * 64 + q * 16), src, 1);
        }
        #pragma unroll
        for (int t = 0; t < 2; t++) {
            int idx = tid + t * 256;
            int row = idx >> 3, sub = idx & 7, half = sub >> 2, q = sub & 3;
            const bf16* src = (half ? Bgl : Bgh)
                              + (size_t)(nt * 64 + row) * DIM + k0 + q * 8;
            CP16(Bb + SWZ(row * 128 + half * 64 + q * 16), src, 1);
        }
    };

    float acc[2][4][4] = {};
    float qsum[4] = {};
    const int nch = 64;
    load_stage(0, 0); CP_COMMIT();
    load_stage(1, 1); CP_COMMIT();
    for (int c = 0; c < nch; c++) {
        if (c + 1 < nch) { CP_WAIT1(); } else { CP_WAIT0(); }
        __syncthreads();
        uint32_t Ab = sbase + (uint32_t)(c & 1) * FIN_STAGE;
        compute_chunk_t<4>(Ab, Ab + 16384u, 0, wm, wn, lane, acc);
        __syncthreads();
        if (c + 2 < nch) { load_stage(c + 2, c & 1); CP_COMMIT(); }
        if ((c & 7) == 7) {
            int nt = c >> 3;
            #pragma unroll
            for (int mt = 0; mt < 2; mt++) {
                #pragma unroll
                for (int bt = 0; bt < 4; bt++) {
                    #pragma unroll
                    for (int i = 0; i < 4; i++) {
                        int cc = nt * 64 + wn + bt * 8 + (lane & 3) * 2 + (i & 1);
                        float hv = fmaxf(acc[mt][bt][i] + sGT[cc], 0.f);
                        qsum[mt * 2 + (i >> 1)] += hv * sW2[cc];
                        acc[mt][bt][i] = 0.f;
                    }
                }
            }
        }
    }

    #pragma unroll
    for (int mt = 0; mt < 2; mt++) {
        #pragma unroll
        for (int ih = 0; ih < 2; ih++) {
            float v = qsum[mt * 2 + ih];
            v += __shfl_xor_sync(0xffffffffu, v, 1);
            v += __shfl_xor_sync(0xffffffffu, v, 2);
            if ((lane & 3) == 0)
                sred[wm + mt * 16 + ih * 8 + (lane >> 2)][w >> 2] = v;
        }
    }
    __syncthreads();
    if (tid < 128)
        out[(size_t)g * PER + tid] = sred[tid][0] + sred[tid][1] + bp2[0];
}

// ---------------- build state_HS = [query | hs | HAts] (hi/lo) --------------
__global__ void build_sHS(const float* __restrict__ query, const float* __restrict__ xf,
                          const float* __restrict__ HAts, bf16* __restrict__ h,
                          bf16* __restrict__ l)
{
    int g = blockIdx.x, c = threadIdx.x;
    bf16 a, b;
    split2(query[g * DIM + c], a, b);
    h[g * 768 + c] = a; l[g * 768 + c] = b;
    split2(xf[(size_t)(3 * g) * DIM + c], a, b);
    h[g * 768 + 256 + c] = a; l[g * 768 + 256 + c] = b;
    split2(HAts[g * DIM + c], a, b);
    h[g * 768 + 512 + c] = a; l[g * 768 + 512 + c] = b;
}

// ---------------- launcher --------------------------------------------------
extern "C" void kernel_launch(void* const* d_in, const int* in_sizes, int n_in,
                              void* d_out, int out_size)
{
    const float* NEs   = (const float*)d_in[0];
    const float* nodes = (const float*)d_in[1];
    const float* query = (const float*)d_in[2];
    const int*   act   = (const int*)d_in[4];
    const float* Wa    = (const float*)d_in[5];
    const float* ba    = (const float*)d_in[6];
    const float* Wc0   = (const float*)d_in[7];
    const float* bc0   = (const float*)d_in[8];
    const float* Wc1   = (const float*)d_in[9];
    const float* bc1   = (const float*)d_in[10];
    const float* Wd1   = (const float*)d_in[11];
    const float* Wc2   = (const float*)d_in[12];
    const float* bc2   = (const float*)d_in[13];
    const float* Wc3   = (const float*)d_in[14];
    const float* bc3   = (const float*)d_in[15];
    const float* Wd3   = (const float*)d_in[16];
    const float* Wp1   = (const float*)d_in[17];
    const float* bp1   = (const float*)d_in[18];
    const float* Wp2   = (const float*)d_in[19];
    const float* bp2   = (const float*)d_in[20];
    float* out = (float*)d_out;

    int tcn_max = tcn_dyn(4, 8);
    cudaFuncSetAttribute(fused_hats, cudaFuncAttributeMaxDynamicSharedMemorySize, FH_DYN);
    cudaFuncSetAttribute(tcn64<0>,  cudaFuncAttributeMaxDynamicSharedMemorySize, tcn_max);
    cudaFuncSetAttribute(tcn64<1>,  cudaFuncAttributeMaxDynamicSharedMemorySize, tcn_max);
    cudaFuncSetAttribute(final_mma, cudaFuncAttributeMaxDynamicSharedMemorySize, FIN_DYN);

    bf16 *hh, *hl, *seqh, *seql, *x1h, *x1l, *x2h, *x2l;
    bf16 *wah, *wal, *wc0h, *wc0l, *wc1h, *wc1l, *wc2h, *wc2l, *wc3h, *wc3l;
    bf16 *wd1h, *wd1l, *wd3h, *wd3l, *wp1th, *wp1tl, *wp1bh, *wp1bl, *sHSh, *sHSl;
    float *HAts, *seqf, *x2f, *GT;
    cudaGetSymbolAddress((void**)&hh,   g_hh);    cudaGetSymbolAddress((void**)&hl,   g_hl);
    cudaGetSymbolAddress((void**)&HAts, g_HAts);
    cudaGetSymbolAddress((void**)&seqf, g_seqf);
    cudaGetSymbolAddress((void**)&seqh, g_seqh);  cudaGetSymbolAddress((void**)&seql, g_seql);
    cudaGetSymbolAddress((void**)&x1h,  g_x1h);   cudaGetSymbolAddress((void**)&x1l,  g_x1l);
    cudaGetSymbolAddress((void**)&x2f,  g_x2f);
    cudaGetSymbolAddress((void**)&x2h,  g_x2h);   cudaGetSymbolAddress((void**)&x2l,  g_x2l);
    cudaGetSymbolAddress((void**)&wah,  g_wah);   cudaGetSymbolAddress((void**)&wal,  g_wal);
    cudaGetSymbolAddress((void**)&wc0h, g_wc0h);  cudaGetSymbolAddress((void**)&wc0l, g_wc0l);
    cudaGetSymbolAddress((void**)&wc1h, g_wc1h);  cudaGetSymbolAddress((void**)&wc1l, g_wc1l);
    cudaGetSymbolAddress((void**)&wc2h, g_wc2h);  cudaGetSymbolAddress((void**)&wc2l, g_wc2l);
    cudaGetSymbolAddress((void**)&wc3h, g_wc3h);  cudaGetSymbolAddress((void**)&wc3l, g_wc3l);
    cudaGetSymbolAddress((void**)&wd1h, g_wd1h);  cudaGetSymbolAddress((void**)&wd1l, g_wd1l);
    cudaGetSymbolAddress((void**)&wd3h, g_wd3h);  cudaGetSymbolAddress((void**)&wd3l, g_wd3l);
    cudaGetSymbolAddress((void**)&wp1th, g_wp1th); cudaGetSymbolAddress((void**)&wp1tl, g_wp1tl);
    cudaGetSymbolAddress((void**)&wp1bh, g_wp1bh); cudaGetSymbolAddress((void**)&wp1bl, g_wp1bl);
    cudaGetSymbolAddress((void**)&sHSh, g_sHSh);  cudaGetSymbolAddress((void**)&sHSl, g_sHSl);
    cudaGetSymbolAddress((void**)&GT,   g_GT);

    // 0) weight prep
    split_weights<<<SPLITW_BLOCKS, 256>>>(Wa, Wc0, Wc1, Wc2, Wc3, Wd1, Wd3, Wp1,
        wah, wal, wc0h, wc0l, wc1h, wc1l, wc2h, wc2l, wc3h, wc3l,
        wd1h, wd1l, wd3h, wd3l, wp1th, wp1tl, wp1bh, wp1bl);

    // 1) hats + segment max + state_seq (fused; one block per group)
    fused_hats<<<GRP, 512, FH_DYN>>>(NEs, wah, wal, ba, nodes, act,
        hh, hl, HAts, seqf, seqh, seql);

    // 2) TCN (launches 2-5; -s 5 profiles layer 3)
    tcn64<0><<<dim3(4, 24), 128, tcn_dyn(3, 1)>>>(seqh, seql, wc0h, wc0l,
        nullptr, nullptr, bc0, seqf, nullptr, x1h, x1l, SEQL, 256, 256, 3, 1, 1);
    tcn64<1><<<dim3(8, 24), 128, tcn_dyn(4, 2)>>>(x1h, x1l, wc1h, wc1l,
        wd1h, wd1l, bc1, nullptr, x2f, x2h, x2l, SEQL, 512, 256, 4, 2, 1);
    tcn64<0><<<dim3(8, 24), 128, tcn_dyn(3, 4)>>>(x2h, x2l, wc2h, wc2l,
        nullptr, nullptr, bc2, x2f, nullptr, x1h, x1l, SEQL, 512, 512, 3, 4, 1);
    tcn64<1><<<dim3(4, 24), 128, tcn_dyn(4, 8)>>>(x1h, x1l, wc3h, wc3l,
        wd3h, wd3l, bc3, nullptr, x2f, nullptr, nullptr, SEQL, 256, 512, 4, 8, 1);

    // 3) state_HS and group term GT = sHS @ Wp1top + bp1
    build_sHS<<<GRP, DIM>>>(query, x2f, HAts, sHSh, sHSl);
    tcn64<0><<<dim3(8, 8), 128, tcn_dyn(1, 0)>>>(sHSh, sHSl, wp1th, wp1tl,
        nullptr, nullptr, bp1, nullptr, GT, nullptr, nullptr, GRP, HID, 768, 1, 0, 0);

    // 4) fused final GEMM + Wp2 reduction
    final_mma<<<GRP, 256, FIN_DYN>>>(hh, hl, wp1bh, wp1bl, GT, Wp2, bp2, out);
}

// round 10
// speedup vs baseline: 1.4529x; 1.4529x over previous
#include <cuda_runtime.h>
#include <cuda_bf16.h>
#include <cstdint>

#define N_TOT 65536
#define GRP   512
#define PER   128
#define DIM   256
#define SEQL  1534
#define HID   512
#define KCH   32

typedef __nv_bfloat16 bf16;

// ---------------- scratch (device globals; no allocation allowed) ----------
__device__ bf16  g_NEh [N_TOT * DIM];
__device__ bf16  g_NEl [N_TOT * DIM];
__device__ bf16  g_hh  [N_TOT * DIM];
__device__ bf16  g_hl  [N_TOT * DIM];
__device__ float g_HAts[GRP * DIM];
__device__ float g_seqf[1536 * DIM];
__device__ bf16  g_seqh[1536 * DIM];
__device__ bf16  g_seql[1536 * DIM];
__device__ bf16  g_x1h [1536 * 512];
__device__ bf16  g_x1l [1536 * 512];
__device__ float g_x2f [1536 * 512];
__device__ bf16  g_x2h [1536 * 512];
__device__ bf16  g_x2l [1536 * 512];
__device__ bf16  g_wah [DIM * DIM];
__device__ bf16  g_wal [DIM * DIM];
__device__ bf16  g_wc0h[3 * 256 * 256];
__device__ bf16  g_wc0l[3 * 256 * 256];
__device__ bf16  g_wc1h[3 * 512 * 256];
__device__ bf16  g_wc1l[3 * 512 * 256];
__device__ bf16  g_wc2h[3 * 512 * 512];
__device__ bf16  g_wc2l[3 * 512 * 512];
__device__ bf16  g_wc3h[3 * 256 * 512];
__device__ bf16  g_wc3l[3 * 256 * 512];
__device__ bf16  g_wd1h[512 * 256];
__device__ bf16  g_wd1l[512 * 256];
__device__ bf16  g_wd3h[256 * 512];
__device__ bf16  g_wd3l[256 * 512];
__device__ bf16  g_wp1th[512 * 768];
__device__ bf16  g_wp1tl[512 * 768];
__device__ bf16  g_wp1bh[512 * 256];
__device__ bf16  g_wp1bl[512 * 256];
__device__ bf16  g_sHSh[GRP * 768];
__device__ bf16  g_sHSl[GRP * 768];
__device__ float g_GT  [GRP * 512];

// ---------------- low-level helpers -----------------------------------------
__device__ __forceinline__ uint32_t smem_u32(const void* p) {
    uint32_t a;
    asm("{ .reg .u64 t; cvta.to.shared.u64 t, %1; cvt.u32.u64 %0, t; }"
        : "=r"(a) : "l"(p));
    return a;
}
static __device__ __forceinline__ uint32_t SWZ(uint32_t off) {
    return off ^ ((off >> 3) & 0x70);
}
__device__ __forceinline__ void mma_bf16(float* c, const uint32_t* a, const uint32_t* b) {
    asm volatile(
        "mma.sync.aligned.m16n8k16.row.col.f32.bf16.bf16.f32 "
        "{%0,%1,%2,%3}, {%4,%5,%6,%7}, {%8,%9}, {%0,%1,%2,%3};\n"
        : "+f"(c[0]), "+f"(c[1]), "+f"(c[2]), "+f"(c[3])
        : "r"(a[0]), "r"(a[1]), "r"(a[2]), "r"(a[3]), "r"(b[0]), "r"(b[1]));
}
__device__ __forceinline__ void ldm_x4(uint32_t* r, uint32_t a) {
    asm volatile("ldmatrix.sync.aligned.m8n8.x4.shared.b16 {%0,%1,%2,%3}, [%4];"
        : "=r"(r[0]), "=r"(r[1]), "=r"(r[2]), "=r"(r[3]) : "r"(a));
}
#define CP16(dst, src, pred) do {                                              \
    int _sz = (pred) ? 16 : 0;                                                 \
    asm volatile("cp.async.cg.shared.global [%0], [%1], 16, %2;"               \
        :: "r"(dst), "l"(src), "r"(_sz) : "memory"); } while (0)
#define CP_COMMIT() asm volatile("cp.async.commit_group;" ::: "memory")
#define CP_WAIT1()  asm volatile("cp.async.wait_group 1;" ::: "memory")
#define CP_WAIT0()  asm volatile("cp.async.wait_group 0;" ::: "memory")

// ---------------- split helpers ---------------------------------------------
__device__ __forceinline__ void split2(float v, bf16& h, bf16& l) {
    h = __float2bfloat16(v);
    l = __float2bfloat16(v - __bfloat162float(h));
}
__global__ void split_arr(const float* __restrict__ x, bf16* __restrict__ h,
                          bf16* __restrict__ l, int n)
{
    int i = blockIdx.x * 256 + threadIdx.x;
    if (i < n) { bf16 a, b; split2(x[i], a, b); h[i] = a; l[i] = b; }
}
__device__ __forceinline__ void d_tsplit(const float* w, bf16* h, bf16* l,
                                         int K, int N, int i)
{
    if (i < K * N) {
        int k = i / N, n = i % N;
        bf16 a, b; split2(w[i], a, b);
        h[(size_t)n * K + k] = a;
        l[(size_t)n * K + k] = b;
    }
}
__device__ __forceinline__ void d_conv(const float* w, bf16* h, bf16* l,
                                       int Cout, int Cin, int i)
{
    if (i < Cout * Cin * 3) {
        int j  = i % 3;
        int ci = (i / 3) % Cin;
        int co = i / (3 * Cin);
        bf16 a, b; split2(w[i], a, b);
        size_t d = ((size_t)j * Cout + co) * Cin + ci;
        h[d] = a; l[d] = b;
    }
}
__device__ __forceinline__ void d_arr(const float* w, bf16* h, bf16* l, int n, int i)
{
    if (i < n) { bf16 a, b; split2(w[i], a, b); h[i] = a; l[i] = b; }
}

__global__ void split_weights(
    const float* Wa, const float* Wc0, const float* Wc1, const float* Wc2,
    const float* Wc3, const float* Wd1, const float* Wd3, const float* Wp1,
    bf16* wah, bf16* wal, bf16* wc0h, bf16* wc0l, bf16* wc1h, bf16* wc1l,
    bf16* wc2h, bf16* wc2l, bf16* wc3h, bf16* wc3l, bf16* wd1h, bf16* wd1l,
    bf16* wd3h, bf16* wd3l, bf16* wp1th, bf16* wp1tl, bf16* wp1bh, bf16* wp1bl)
{
    int b = blockIdx.x, t = threadIdx.x;
    if (b < 256)        { d_tsplit(Wa, wah, wal, 256, 256, b * 256 + t); return; }
    b -= 256;
    if (b < 768)        { d_conv(Wc0, wc0h, wc0l, 256, 256, b * 256 + t); return; }
    b -= 768;
    if (b < 1536)       { d_conv(Wc1, wc1h, wc1l, 512, 256, b * 256 + t); return; }
    b -= 1536;
    if (b < 3072)       { d_conv(Wc2, wc2h, wc2l, 512, 512, b * 256 + t); return; }
    b -= 3072;
    if (b < 1536)       { d_conv(Wc3, wc3h, wc3l, 256, 512, b * 256 + t); return; }
    b -= 1536;
    if (b < 512)        { d_arr(Wd1, wd1h, wd1l, 512 * 256, b * 256 + t); return; }
    b -= 512;
    if (b < 512)        { d_arr(Wd3, wd3h, wd3l, 256 * 512, b * 256 + t); return; }
    b -= 512;
    if (b < 1536)       { d_tsplit(Wp1, wp1th, wp1tl, 768, 512, b * 256 + t); return; }
    b -= 1536;
    if (b < 512)        { d_tsplit(Wp1 + 768 * 512, wp1bh, wp1bl, 256, 512, b * 256 + t); }
}
#define SPLITW_BLOCKS (256 + 768 + 1536 + 3072 + 1536 + 512 + 512 + 1536 + 512)

// ---------------- warp compute for one k32 chunk -----------------------------
template<int NBT>
__device__ __forceinline__ void compute_chunk_t(uint32_t Ab, uint32_t Bb, int aoff,
                                                int wm, int wn, int lane,
                                                float acc[2][NBT][4])
{
    int l7 = lane & 7;
    int b3 = (lane >> 3) & 1;
    int b4 = (lane >> 4) & 1;
    #pragma unroll
    for (int ks = 0; ks < 2; ks++) {
        int colb = ks * 32;
        uint32_t bh[NBT][2], bl[NBT][2];
        #pragma unroll
        for (int pp = 0; pp < NBT / 2; pp++) {
            int nrow = wn + pp * 16 + b4 * 8 + l7;
            uint32_t off = nrow * 128 + colb + b3 * 16;
            uint32_t rh[4], rl[4];
            ldm_x4(rh, Bb + SWZ(off));
            ldm_x4(rl, Bb + SWZ(off + 64));
            bh[pp * 2 + 0][0] = rh[0]; bh[pp * 2 + 0][1] = rh[1];
            bh[pp * 2 + 1][0] = rh[2]; bh[pp * 2 + 1][1] = rh[3];
            bl[pp * 2 + 0][0] = rl[0]; bl[pp * 2 + 0][1] = rl[1];
            bl[pp * 2 + 1][0] = rl[2]; bl[pp * 2 + 1][1] = rl[3];
        }
        #pragma unroll
        for (int mt = 0; mt < 2; mt++) {
            int arow = aoff + wm + mt * 16 + b3 * 8 + l7;
            uint32_t off = arow * 128 + colb + b4 * 16;
            uint32_t ah[4], al[4];
            ldm_x4(ah, Ab + SWZ(off));
            ldm_x4(al, Ab + SWZ(off + 64));
            #pragma unroll
            for (int bt = 0; bt < NBT; bt++) {
                mma_bf16(acc[mt][bt], ah, bh[bt]);
                mma_bf16(acc[mt][bt], ah, bl[bt]);
                mma_bf16(acc[mt][bt], al, bh[bt]);
            }
        }
    }
}

// ---------------- hats GEMM + fused segmax/act/state_seq ---------------------
// grid (2, GRP): blockIdx.y = group (128 rows), blockIdx.x = 128-col slice.
// Each block holds ALL rows of its group -> computes full col-max for its
// slice, gathers the act row, and writes its share of state_seq rows.
#define G128_STAGE 32768u
#define G128_DYN   (2 * 32768 + 1024)
__global__ __launch_bounds__(256, 2)
void hats_gemm(const bf16* __restrict__ Agh, const bf16* __restrict__ Agl,
               const bf16* __restrict__ Wgh, const bf16* __restrict__ Wgl,
               const float* __restrict__ bias,
               const float* __restrict__ nodes, const int* __restrict__ act,
               bf16* __restrict__ Ch, bf16* __restrict__ Cl,
               float* __restrict__ HAts, float* __restrict__ seqf,
               bf16* __restrict__ seqh, bf16* __restrict__ seql)
{
    extern __shared__ char dyn[];
    __shared__ float smax[4][128];
    uint32_t sbase = (smem_u32(dyn) + 1023u) & ~1023u;
    int tid = threadIdx.x, lane = tid & 31, w = tid >> 5;
    int wm = (w & 3) * 32, wn = (w >> 2) * 64;
    int g = blockIdx.y;
    int row0 = g * 128, col0 = blockIdx.x * 128;
    const int nch = 8;   // K = 256

    auto load_stage = [&](int c, int s) {
        int k0 = c * KCH;
        uint32_t Ab = sbase + (uint32_t)s * G128_STAGE;
        uint32_t Bb = Ab + 16384u;
        #pragma unroll
        for (int t = 0; t < 4; t++) {
            int idx = tid + t * 256;
            int row = idx >> 3, sub = idx & 7, half = sub >> 2, q = sub & 3;
            const bf16* src = (half ? Agl : Agh) + (size_t)(row0 + row) * 256 + k0 + q * 8;
            CP16(Ab + SWZ(row * 128 + half * 64 + q * 16), src, 1);
        }
        #pragma unroll
        for (int t = 0; t < 4; t++) {
            int idx = tid + t * 256;
            int row = idx >> 3, sub = idx & 7, half = sub >> 2, q = sub & 3;
            const bf16* src = (half ? Wgl : Wgh) + (size_t)(col0 + row) * 256 + k0 + q * 8;
            CP16(Bb + SWZ(row * 128 + half * 64 + q * 16), src, 1);
        }
    };

    float acc[2][8][4] = {};
    load_stage(0, 0); CP_COMMIT();
    load_stage(1, 1); CP_COMMIT();
    for (int c = 0; c < nch; c++) {
        if (c + 1 < nch) { CP_WAIT1(); } else { CP_WAIT0(); }
        __syncthreads();
        uint32_t Ab = sbase + (uint32_t)(c & 1) * G128_STAGE;
        compute_chunk_t<8>(Ab, Ab + 16384u, 0, wm, wn, lane, acc);
        __syncthreads();
        if (c + 2 < nch) { load_stage(c + 2, c & 1); CP_COMMIT(); }
    }

    // ---- epilogue: hats hi/lo + col-max + act-row gather ----
    int ra = (g < GRP - 1) ? act[g] : -1;
    float cmax[16];
    #pragma unroll
    for (int i = 0; i < 16; i++) cmax[i] = 0.f;   // relu outputs >= 0

    #pragma unroll
    for (int mt = 0; mt < 2; mt++) {
        #pragma unroll
        for (int ih = 0; ih < 2; ih++) {
            int rl = wm + mt * 16 + ih * 8 + (lane >> 2);
            #pragma unroll
            for (int bt = 0; bt < 8; bt++) {
                int ccl = wn + bt * 8 + (lane & 3) * 2;
                int cc = col0 + ccl;
                float v0 = fmaxf(acc[mt][bt][ih * 2 + 0] + bias[cc], 0.f);
                float v1 = fmaxf(acc[mt][bt][ih * 2 + 1] + bias[cc + 1], 0.f);
                size_t idx = (size_t)(row0 + rl) * 256 + cc;
                bf16 h0, l0, h1, l1;
                split2(v0, h0, l0); split2(v1, h1, l1);
                __nv_bfloat162 hp = {h0, h1}, lp = {l0, l1};
                *(__nv_bfloat162*)(Ch + idx) = hp;
                *(__nv_bfloat162*)(Cl + idx) = lp;
                cmax[bt * 2]     = fmaxf(cmax[bt * 2], v0);
                cmax[bt * 2 + 1] = fmaxf(cmax[bt * 2 + 1], v1);
                if (rl == ra) {
                    size_t sid = (size_t)(3 * g + 2) * 256 + cc;
                    *(float2*)(seqf + sid) = make_float2(v0, v1);
                    *(__nv_bfloat162*)(seqh + sid) = hp;
                    *(__nv_bfloat162*)(seql + sid) = lp;
                }
            }
        }
    }
    #pragma unroll
    for (int i = 0; i < 16; i++) {
        float m = cmax[i];
        m = fmaxf(m, __shfl_xor_sync(0xffffffffu, m, 4));
        m = fmaxf(m, __shfl_xor_sync(0xffffffffu, m, 8));
        m = fmaxf(m, __shfl_xor_sync(0xffffffffu, m, 16));
        cmax[i] = m;
    }
    if ((lane >> 2) == 0) {
        #pragma unroll
        for (int bt = 0; bt < 8; bt++) {
            int ccl = wn + bt * 8 + lane * 2;
            smax[w & 3][ccl]     = cmax[bt * 2];
            smax[w & 3][ccl + 1] = cmax[bt * 2 + 1];
        }
    }
    __syncthreads();
    if (tid < 128) {
        int cc = col0 + tid;
        float m = fmaxf(fmaxf(smax[0][tid], smax[1][tid]),
                        fmaxf(smax[2][tid], smax[3][tid]));
        HAts[g * 256 + cc] = m;
        bf16 a, b;
        float nv = nodes[g * 256 + cc];
        if (g < GRP - 1) {
            size_t sid = (size_t)(3 * g + 1) * 256 + cc;
            seqf[sid] = m;
            split2(m, a, b); seqh[sid] = a; seql[sid] = b;
            sid = (size_t)(3 * g) * 256 + cc;
            seqf[sid] = nv;
            split2(nv, a, b); seqh[sid] = a; seql[sid] = b;
        } else {
            size_t sid = (size_t)(SEQL - 1) * 256 + cc;
            seqf[sid] = nv;
            split2(nv, a, b); seqh[sid] = a; seql[sid] = b;
        }
    }
}

// ---------------- TCN with halo (dynamic stage size) -------------------------
template<int DUAL>
__global__ __launch_bounds__(128, 3)
void tcn64(const bf16* __restrict__ Agh, const bf16* __restrict__ Agl,
           const bf16* __restrict__ Wgh, const bf16* __restrict__ Wgl,
           const bf16* __restrict__ Wdh, const bf16* __restrict__ Wdl,
           const float* __restrict__ bias, const float* __restrict__ Rf,
           float* __restrict__ Cf, bf16* __restrict__ Ch, bf16* __restrict__ Cl,
           int Mv, int N, int K, int npass, int dil, int doRelu)
{
    extern __shared__ char dyn[];
    uint32_t sbase = (smem_u32(dyn) + 1023u) & ~1023u;
    int tid = threadIdx.x, lane = tid & 31, w = tid >> 5;
    int wm = (w & 1) * 32, wn = (w >> 1) * 32;
    int row0 = blockIdx.y * 64, col0 = blockIdx.x * 64;
    int halo = (npass >= 3) ? 2 * dil : 0;
    int nrows = 64 + halo;
    uint32_t Abytes = (uint32_t)nrows * 128u;
    uint32_t stage = (Abytes + (uint32_t)npass * 8192u + 1023u) & ~1023u;
    int nch = K / KCH;

    auto load_stage = [&](int c, int s) {
        int k0 = c * KCH;
        uint32_t Ab = sbase + (uint32_t)s * stage;
        for (int idx = tid; idx < nrows * 8; idx += 128) {
            int row = idx >> 3, sub = idx & 7, half = sub >> 2, q = sub & 3;
            int ga = row0 - halo + row;
            const bf16* src = (half ? Agl : Agh)
                              + (size_t)(ga < 0 ? 0 : ga) * K + k0 + q * 8;
            CP16(Ab + SWZ(row * 128 + half * 64 + q * 16), src, ga >= 0);
        }
        for (int p = 0; p < npass; p++) {
            const bf16* Ph = (p < 3) ? Wgh + (size_t)p * N * K : Wdh;
            const bf16* Pl = (p < 3) ? Wgl + (size_t)p * N * K : Wdl;
            uint32_t Bb = Ab + Abytes + (uint32_t)p * 8192u;
            #pragma unroll
            for (int t = 0; t < 4; t++) {
                int idx = tid + t * 128;
                int row = idx >> 3, sub = idx & 7, half = sub >> 2, q = sub & 3;
                const bf16* src = (half ? Pl : Ph) + (size_t)(col0 + row) * K + k0 + q * 8;
                CP16(Bb + SWZ(row * 128 + half * 64 + q * 16), src, 1);
            }
        }
    };

    float acc[2][4][4] = {};
    float accR[DUAL ? 2 : 1][DUAL ? 4 : 1][DUAL ? 4 : 1] = {};
    load_stage(0, 0); CP_COMMIT();
    if (nch > 1) { load_stage(1, 1); CP_COMMIT(); }
    for (int c = 0; c < nch; c++) {
        if (c + 1 < nch) { CP_WAIT1(); } else { CP_WAIT0(); }
        __syncthreads();
        uint32_t Ab = sbase + (uint32_t)(c & 1) * stage;
        for (int p = 0; p < npass; p++) {
            int aoff = (p < 3) ? p * dil : 2 * dil;
            uint32_t Bb = Ab + Abytes + (uint32_t)p * 8192u;
            if (DUAL && p == 3)
                compute_chunk_t<4>(Ab, Bb, aoff, wm, wn, lane, (float (*)[4][4])accR);
            else
                compute_chunk_t<4>(Ab, Bb, aoff, wm, wn, lane, acc);
        }
        __syncthreads();
        if (c + 2 < nch) { load_stage(c + 2, c & 1); CP_COMMIT(); }
    }

    #pragma unroll
    for (int mt = 0; mt < 2; mt++) {
        #pragma unroll
        for (int ih = 0; ih < 2; ih++) {
            int rr = row0 + wm + mt * 16 + ih * 8 + (lane >> 2);
            if (rr >= Mv) continue;
            #pragma unroll
            for (int bt = 0; bt < 4; bt++) {
                int cc = col0 + wn + bt * 8 + (lane & 3) * 2;
                size_t idx = (size_t)rr * N + cc;
                float v0 = acc[mt][bt][ih * 2 + 0] + bias[cc];
                float v1 = acc[mt][bt][ih * 2 + 1] + bias[cc + 1];
                if (doRelu) { v0 = fmaxf(v0, 0.f); v1 = fmaxf(v1, 0.f); }
                if (DUAL) {
                    v0 = fmaxf(v0 + accR[mt][bt][ih * 2 + 0], 0.f);
                    v1 = fmaxf(v1 + accR[mt][bt][ih * 2 + 1], 0.f);
                } else if (Rf) {
                    float2 rv = *(const float2*)(Rf + idx);
                    v0 = fmaxf(v0 + rv.x, 0.f);
                    v1 = fmaxf(v1 + rv.y, 0.f);
                }
                if (Cf) *(float2*)(Cf + idx) = make_float2(v0, v1);
                if (Ch) {
                    bf16 h0, l0, h1, l1;
                    split2(v0, h0, l0); split2(v1, h1, l1);
                    __nv_bfloat162 hp = {h0, h1}, lp = {l0, l1};
                    *(__nv_bfloat162*)(Ch + idx) = hp;
                    *(__nv_bfloat162*)(Cl + idx) = lp;
                }
            }
        }
    }
}

static int tcn_dyn(int npass, int dil) {
    int halo = (npass >= 3) ? 2 * dil : 0;
    unsigned Abytes = (unsigned)(64 + halo) * 128u;
    unsigned stage = (Abytes + (unsigned)npass * 8192u + 1023u) & ~1023u;
    return (int)(2 * stage + 1024);
}

// ---------------- fused final: out = relu(hats@Wp1bot + GT[g]) @ Wp2 + bp2 --
#define FIN_STAGE 24576u
#define FIN_DYN   (2 * 24576 + 1024)
__global__ __launch_bounds__(256, 2)
void final_mma(const bf16* __restrict__ Hh, const bf16* __restrict__ Hl,
               const bf16* __restrict__ Bgh, const bf16* __restrict__ Bgl,
               const float* __restrict__ GT, const float* __restrict__ W2,
               const float* __restrict__ bp2, float* __restrict__ out)
{
    extern __shared__ char dyn[];
    __shared__ float sGT[512], sW2[512], sred[128][2];
    uint32_t sbase = (smem_u32(dyn) + 1023u) & ~1023u;
    int g = blockIdx.x;
    int tid = threadIdx.x, lane = tid & 31, w = tid >> 5;
    int wm = (w & 3) * 32, wn = (w >> 2) * 32;

    for (int i = tid; i < 512; i += 256) {
        sGT[i] = GT[(size_t)g * 512 + i];
        sW2[i] = W2[i];
    }

    const bf16* Ah = Hh + (size_t)g * PER * DIM;
    const bf16* Al = Hl + (size_t)g * PER * DIM;

    auto load_stage = [&](int c, int s) {
        int nt = c >> 3;
        int k0 = (c & 7) * KCH;
        uint32_t Ab = sbase + (uint32_t)s * FIN_STAGE;
        uint32_t Bb = Ab + 16384u;
        #pragma unroll
        for (int t = 0; t < 4; t++) {
            int idx = tid + t * 256;
            int row = idx >> 3, sub = idx & 7, half = sub >> 2, q = sub & 3;
            const bf16* src = (half ? Al : Ah) + (size_t)row * DIM + k0 + q * 8;
            CP16(Ab + SWZ(row * 128 + half * 64 + q * 16), src, 1);
        }
        #pragma unroll
        for (int t = 0; t < 2; t++) {
            int idx = tid + t * 256;
            int row = idx >> 3, sub = idx & 7, half = sub >> 2, q = sub & 3;
            const bf16* src = (half ? Bgl : Bgh)
                              + (size_t)(nt * 64 + row) * DIM + k0 + q * 8;
            CP16(Bb + SWZ(row * 128 + half * 64 + q * 16), src, 1);
        }
    };

    float acc[2][4][4] = {};
    float qsum[4] = {};
    const int nch = 64;
    load_stage(0, 0); CP_COMMIT();
    load_stage(1, 1); CP_COMMIT();
    for (int c = 0; c < nch; c++) {
        if (c + 1 < nch) { CP_WAIT1(); } else { CP_WAIT0(); }
        __syncthreads();
        uint32_t Ab = sbase + (uint32_t)(c & 1) * FIN_STAGE;
        compute_chunk_t<4>(Ab, Ab + 16384u, 0, wm, wn, lane, acc);
        __syncthreads();
        if (c + 2 < nch) { load_stage(c + 2, c & 1); CP_COMMIT(); }
        if ((c & 7) == 7) {
            int nt = c >> 3;
            #pragma unroll
            for (int mt = 0; mt < 2; mt++) {
                #pragma unroll
                for (int bt = 0; bt < 4; bt++) {
                    #pragma unroll
                    for (int i = 0; i < 4; i++) {
                        int cc = nt * 64 + wn + bt * 8 + (lane & 3) * 2 + (i & 1);
                        float hv = fmaxf(acc[mt][bt][i] + sGT[cc], 0.f);
                        qsum[mt * 2 + (i >> 1)] += hv * sW2[cc];
                        acc[mt][bt][i] = 0.f;
                    }
                }
            }
        }
    }

    #pragma unroll
    for (int mt = 0; mt < 2; mt++) {
        #pragma unroll
        for (int ih = 0; ih < 2; ih++) {
            float v = qsum[mt * 2 + ih];
            v += __shfl_xor_sync(0xffffffffu, v, 1);
            v += __shfl_xor_sync(0xffffffffu, v, 2);
            if ((lane & 3) == 0)
                sred[wm + mt * 16 + ih * 8 + (lane >> 2)][w >> 2] = v;
        }
    }
    __syncthreads();
    if (tid < 128)
        out[(size_t)g * PER + tid] = sred[tid][0] + sred[tid][1] + bp2[0];
}

// ---------------- build state_HS = [query | hs | HAts] (hi/lo) --------------
__global__ void build_sHS(const float* __restrict__ query, const float* __restrict__ xf,
                          const float* __restrict__ HAts, bf16* __restrict__ h,
                          bf16* __restrict__ l)
{
    int g = blockIdx.x, c = threadIdx.x;
    bf16 a, b;
    split2(query[g * DIM + c], a, b);
    h[g * 768 + c] = a; l[g * 768 + c] = b;
    split2(xf[(size_t)(3 * g) * DIM + c], a, b);
    h[g * 768 + 256 + c] = a; l[g * 768 + 256 + c] = b;
    split2(HAts[g * DIM + c], a, b);
    h[g * 768 + 512 + c] = a; l[g * 768 + 512 + c] = b;
}

// ---------------- launcher --------------------------------------------------
extern "C" void kernel_launch(void* const* d_in, const int* in_sizes, int n_in,
                              void* d_out, int out_size)
{
    const float* NEs   = (const float*)d_in[0];
    const float* nodes = (const float*)d_in[1];
    const float* query = (const float*)d_in[2];
    const int*   act   = (const int*)d_in[4];
    const float* Wa    = (const float*)d_in[5];
    const float* ba    = (const float*)d_in[6];
    const float* Wc0   = (const float*)d_in[7];
    const float* bc0   = (const float*)d_in[8];
    const float* Wc1   = (const float*)d_in[9];
    const float* bc1   = (const float*)d_in[10];
    const float* Wd1   = (const float*)d_in[11];
    const float* Wc2   = (const float*)d_in[12];
    const float* bc2   = (const float*)d_in[13];
    const float* Wc3   = (const float*)d_in[14];
    const float* bc3   = (const float*)d_in[15];
    const float* Wd3   = (const float*)d_in[16];
    const float* Wp1   = (const float*)d_in[17];
    const float* bp1   = (const float*)d_in[18];
    const float* Wp2   = (const float*)d_in[19];
    const float* bp2   = (const float*)d_in[20];
    float* out = (float*)d_out;

    int tcn_max = tcn_dyn(4, 8);
    cudaFuncSetAttribute(hats_gemm, cudaFuncAttributeMaxDynamicSharedMemorySize, G128_DYN);
    cudaFuncSetAttribute(tcn64<0>,  cudaFuncAttributeMaxDynamicSharedMemorySize, tcn_max);
    cudaFuncSetAttribute(tcn64<1>,  cudaFuncAttributeMaxDynamicSharedMemorySize, tcn_max);
    cudaFuncSetAttribute(final_mma, cudaFuncAttributeMaxDynamicSharedMemorySize, FIN_DYN);

    bf16 *NEh, *NEl, *hh, *hl, *seqh, *seql, *x1h, *x1l, *x2h, *x2l;
    bf16 *wah, *wal, *wc0h, *wc0l, *wc1h, *wc1l, *wc2h, *wc2l, *wc3h, *wc3l;
    bf16 *wd1h, *wd1l, *wd3h, *wd3l, *wp1th, *wp1tl, *wp1bh, *wp1bl, *sHSh, *sHSl;
    float *HAts, *seqf, *x2f, *GT;
    cudaGetSymbolAddress((void**)&NEh,  g_NEh);   cudaGetSymbolAddress((void**)&NEl,  g_NEl);
    cudaGetSymbolAddress((void**)&hh,   g_hh);    cudaGetSymbolAddress((void**)&hl,   g_hl);
    cudaGetSymbolAddress((void**)&HAts, g_HAts);
    cudaGetSymbolAddress((void**)&seqf, g_seqf);
    cudaGetSymbolAddress((void**)&seqh, g_seqh);  cudaGetSymbolAddress((void**)&seql, g_seql);
    cudaGetSymbolAddress((void**)&x1h,  g_x1h);   cudaGetSymbolAddress((void**)&x1l,  g_x1l);
    cudaGetSymbolAddress((void**)&x2f,  g_x2f);
    cudaGetSymbolAddress((void**)&x2h,  g_x2h);   cudaGetSymbolAddress((void**)&x2l,  g_x2l);
    cudaGetSymbolAddress((void**)&wah,  g_wah);   cudaGetSymbolAddress((void**)&wal,  g_wal);
    cudaGetSymbolAddress((void**)&wc0h, g_wc0h);  cudaGetSymbolAddress((void**)&wc0l, g_wc0l);
    cudaGetSymbolAddress((void**)&wc1h, g_wc1h);  cudaGetSymbolAddress((void**)&wc1l, g_wc1l);
    cudaGetSymbolAddress((void**)&wc2h, g_wc2h);  cudaGetSymbolAddress((void**)&wc2l, g_wc2l);
    cudaGetSymbolAddress((void**)&wc3h, g_wc3h);  cudaGetSymbolAddress((void**)&wc3l, g_wc3l);
    cudaGetSymbolAddress((void**)&wd1h, g_wd1h);  cudaGetSymbolAddress((void**)&wd1l, g_wd1l);
    cudaGetSymbolAddress((void**)&wd3h, g_wd3h);  cudaGetSymbolAddress((void**)&wd3l, g_wd3l);
    cudaGetSymbolAddress((void**)&wp1th, g_wp1th); cudaGetSymbolAddress((void**)&wp1tl, g_wp1tl);
    cudaGetSymbolAddress((void**)&wp1bh, g_wp1bh); cudaGetSymbolAddress((void**)&wp1bl, g_wp1bl);
    cudaGetSymbolAddress((void**)&sHSh, g_sHSh);  cudaGetSymbolAddress((void**)&sHSl, g_sHSl);
    cudaGetSymbolAddress((void**)&GT,   g_GT);

    // 0-1) prep
    split_arr<<<(N_TOT * DIM + 255) / 256, 256>>>(NEs, NEh, NEl, N_TOT * DIM);
    split_weights<<<SPLITW_BLOCKS, 256>>>(Wa, Wc0, Wc1, Wc2, Wc3, Wd1, Wd3, Wp1,
        wah, wal, wc0h, wc0l, wc1h, wc1l, wc2h, wc2l, wc3h, wc3l,
        wd1h, wd1l, wd3h, wd3l, wp1th, wp1tl, wp1bh, wp1bl);

    // 2) hats GEMM with fused segmax/act/state_seq (grid.y = group)
    hats_gemm<<<dim3(2, GRP), 256, G128_DYN>>>(NEh, NEl, wah, wal, ba,
        nodes, act, hh, hl, HAts, seqf, seqh, seql);

    // 3) TCN (launches 3-6; -s 5 profiles layer 2: 3-CTA occupancy check)
    tcn64<0><<<dim3(4, 24), 128, tcn_dyn(3, 1)>>>(seqh, seql, wc0h, wc0l,
        nullptr, nullptr, bc0, seqf, nullptr, x1h, x1l, SEQL, 256, 256, 3, 1, 1);
    tcn64<1><<<dim3(8, 24), 128, tcn_dyn(4, 2)>>>(x1h, x1l, wc1h, wc1l,
        wd1h, wd1l, bc1, nullptr, x2f, x2h, x2l, SEQL, 512, 256, 4, 2, 1);
    tcn64<0><<<dim3(8, 24), 128, tcn_dyn(3, 4)>>>(x2h, x2l, wc2h, wc2l,
        nullptr, nullptr, bc2, x2f, nullptr, x1h, x1l, SEQL, 512, 512, 3, 4, 1);
    tcn64<1><<<dim3(4, 24), 128, tcn_dyn(4, 8)>>>(x1h, x1l, wc3h, wc3l,
        wd3h, wd3l, bc3, nullptr, x2f, nullptr, nullptr, SEQL, 256, 512, 4, 8, 1);

    // 4) state_HS and group term GT = sHS @ Wp1top + bp1
    build_sHS<<<GRP, DIM>>>(query, x2f, HAts, sHSh, sHSl);
    tcn64<0><<<dim3(8, 8), 128, tcn_dyn(1, 0)>>>(sHSh, sHSl, wp1th, wp1tl,
        nullptr, nullptr, bp1, nullptr, GT, nullptr, nullptr, GRP, HID, 768, 1, 0, 0);

    // 5) fused final GEMM + Wp2 reduction
    final_mma<<<GRP, 256, FIN_DYN>>>(hh, hl, wp1bh, wp1bl, GT, Wp2, bp2, out);
}

// round 12
// speedup vs baseline: 1.5929x; 1.0963x over previous
#include <cuda_runtime.h>
#include <cuda_bf16.h>
#include <cstdint>

#define N_TOT 65536
#define GRP   512
#define PER   128
#define DIM   256
#define SEQL  1534
#define HID   512
#define KCH   32

typedef __nv_bfloat16 bf16;

// ---------------- scratch (device globals; no allocation allowed) ----------
__device__ bf16  g_hh  [N_TOT * DIM];
__device__ bf16  g_hl  [N_TOT * DIM];
__device__ float g_HAts[GRP * DIM];
__device__ float g_seqf[1536 * DIM];
__device__ bf16  g_seqh[1536 * DIM];
__device__ bf16  g_seql[1536 * DIM];
__device__ bf16  g_x1h [1536 * 512];
__device__ bf16  g_x1l [1536 * 512];
__device__ float g_x2f [1536 * 512];
__device__ bf16  g_x2h [1536 * 512];
__device__ bf16  g_x2l [1536 * 512];
__device__ bf16  g_wah [DIM * DIM];
__device__ bf16  g_wal [DIM * DIM];
__device__ bf16  g_wc0h[3 * 256 * 256];
__device__ bf16  g_wc0l[3 * 256 * 256];
__device__ bf16  g_wc1h[3 * 512 * 256];
__device__ bf16  g_wc1l[3 * 512 * 256];
__device__ bf16  g_wc2h[3 * 512 * 512];
__device__ bf16  g_wc2l[3 * 512 * 512];
__device__ bf16  g_wc3h[3 * 256 * 512];
__device__ bf16  g_wc3l[3 * 256 * 512];
__device__ bf16  g_wd1h[512 * 256];
__device__ bf16  g_wd1l[512 * 256];
__device__ bf16  g_wd3h[256 * 512];
__device__ bf16  g_wd3l[256 * 512];
__device__ bf16  g_wp1th[512 * 768];
__device__ bf16  g_wp1tl[512 * 768];
__device__ bf16  g_wp1bh[512 * 256];
__device__ bf16  g_wp1bl[512 * 256];
__device__ bf16  g_sHSh[GRP * 768];
__device__ bf16  g_sHSl[GRP * 768];
__device__ float g_GT  [GRP * 512];

// ---------------- low-level helpers -----------------------------------------
__device__ __forceinline__ uint32_t smem_u32(const void* p) {
    uint32_t a;
    asm("{ .reg .u64 t; cvta.to.shared.u64 t, %1; cvt.u32.u64 %0, t; }"
        : "=r"(a) : "l"(p));
    return a;
}
static __device__ __forceinline__ uint32_t SWZ(uint32_t off) {
    return off ^ ((off >> 3) & 0x70);
}
__device__ __forceinline__ void mma_bf16(float* c, const uint32_t* a, const uint32_t* b) {
    asm volatile(
        "mma.sync.aligned.m16n8k16.row.col.f32.bf16.bf16.f32 "
        "{%0,%1,%2,%3}, {%4,%5,%6,%7}, {%8,%9}, {%0,%1,%2,%3};\n"
        : "+f"(c[0]), "+f"(c[1]), "+f"(c[2]), "+f"(c[3])
        : "r"(a[0]), "r"(a[1]), "r"(a[2]), "r"(a[3]), "r"(b[0]), "r"(b[1]));
}
__device__ __forceinline__ void ldm_x4(uint32_t* r, uint32_t a) {
    asm volatile("ldmatrix.sync.aligned.m8n8.x4.shared.b16 {%0,%1,%2,%3}, [%4];"
        : "=r"(r[0]), "=r"(r[1]), "=r"(r[2]), "=r"(r[3]) : "r"(a));
}
#define CP16(dst, src, pred) do {                                              \
    int _sz = (pred) ? 16 : 0;                                                 \
    asm volatile("cp.async.cg.shared.global [%0], [%1], 16, %2;"               \
        :: "r"(dst), "l"(src), "r"(_sz) : "memory"); } while (0)
#define CP_COMMIT() asm volatile("cp.async.commit_group;" ::: "memory")
#define CP_WAIT1()  asm volatile("cp.async.wait_group 1;" ::: "memory")
#define CP_WAIT0()  asm volatile("cp.async.wait_group 0;" ::: "memory")

// ---------------- split helpers ---------------------------------------------
__device__ __forceinline__ void split2(float v, bf16& h, bf16& l) {
    h = __float2bfloat16(v);
    l = __float2bfloat16(v - __bfloat162float(h));
}
__device__ __forceinline__ void d_tsplit(const float* w, bf16* h, bf16* l,
                                         int K, int N, int i)
{
    if (i < K * N) {
        int k = i / N, n = i % N;
        bf16 a, b; split2(w[i], a, b);
        h[(size_t)n * K + k] = a;
        l[(size_t)n * K + k] = b;
    }
}
__device__ __forceinline__ void d_conv(const float* w, bf16* h, bf16* l,
                                       int Cout, int Cin, int i)
{
    if (i < Cout * Cin * 3) {
        int j  = i % 3;
        int ci = (i / 3) % Cin;
        int co = i / (3 * Cin);
        bf16 a, b; split2(w[i], a, b);
        size_t d = ((size_t)j * Cout + co) * Cin + ci;
        h[d] = a; l[d] = b;
    }
}
__device__ __forceinline__ void d_arr(const float* w, bf16* h, bf16* l, int n, int i)
{
    if (i < n) { bf16 a, b; split2(w[i], a, b); h[i] = a; l[i] = b; }
}

__global__ void split_weights(
    const float* Wa, const float* Wc0, const float* Wc1, const float* Wc2,
    const float* Wc3, const float* Wd1, const float* Wd3, const float* Wp1,
    bf16* wah, bf16* wal, bf16* wc0h, bf16* wc0l, bf16* wc1h, bf16* wc1l,
    bf16* wc2h, bf16* wc2l, bf16* wc3h, bf16* wc3l, bf16* wd1h, bf16* wd1l,
    bf16* wd3h, bf16* wd3l, bf16* wp1th, bf16* wp1tl, bf16* wp1bh, bf16* wp1bl)
{
    int b = blockIdx.x, t = threadIdx.x;
    if (b < 256)        { d_tsplit(Wa, wah, wal, 256, 256, b * 256 + t); return; }
    b -= 256;
    if (b < 768)        { d_conv(Wc0, wc0h, wc0l, 256, 256, b * 256 + t); return; }
    b -= 768;
    if (b < 1536)       { d_conv(Wc1, wc1h, wc1l, 512, 256, b * 256 + t); return; }
    b -= 1536;
    if (b < 3072)       { d_conv(Wc2, wc2h, wc2l, 512, 512, b * 256 + t); return; }
    b -= 3072;
    if (b < 1536)       { d_conv(Wc3, wc3h, wc3l, 256, 512, b * 256 + t); return; }
    b -= 1536;
    if (b < 512)        { d_arr(Wd1, wd1h, wd1l, 512 * 256, b * 256 + t); return; }
    b -= 512;
    if (b < 512)        { d_arr(Wd3, wd3h, wd3l, 256 * 512, b * 256 + t); return; }
    b -= 512;
    if (b < 1536)       { d_tsplit(Wp1, wp1th, wp1tl, 768, 512, b * 256 + t); return; }
    b -= 1536;
    if (b < 512)        { d_tsplit(Wp1 + 768 * 512, wp1bh, wp1bl, 256, 512, b * 256 + t); }
}
#define SPLITW_BLOCKS (256 + 768 + 1536 + 3072 + 1536 + 512 + 512 + 1536 + 512)

// ---------------- warp compute for one k32 chunk -----------------------------
template<int NBT>
__device__ __forceinline__ void compute_chunk_t(uint32_t Ab, uint32_t Bb, int aoff,
                                                int wm, int wn, int lane,
                                                float acc[2][NBT][4])
{
    int l7 = lane & 7;
    int b3 = (lane >> 3) & 1;
    int b4 = (lane >> 4) & 1;
    #pragma unroll
    for (int ks = 0; ks < 2; ks++) {
        int colb = ks * 32;
        uint32_t bh[NBT][2], bl[NBT][2];
        #pragma unroll
        for (int pp = 0; pp < NBT / 2; pp++) {
            int nrow = wn + pp * 16 + b4 * 8 + l7;
            uint32_t off = nrow * 128 + colb + b3 * 16;
            uint32_t rh[4], rl[4];
            ldm_x4(rh, Bb + SWZ(off));
            ldm_x4(rl, Bb + SWZ(off + 64));
            bh[pp * 2 + 0][0] = rh[0]; bh[pp * 2 + 0][1] = rh[1];
            bh[pp * 2 + 1][0] = rh[2]; bh[pp * 2 + 1][1] = rh[3];
            bl[pp * 2 + 0][0] = rl[0]; bl[pp * 2 + 0][1] = rl[1];
            bl[pp * 2 + 1][0] = rl[2]; bl[pp * 2 + 1][1] = rl[3];
        }
        #pragma unroll
        for (int mt = 0; mt < 2; mt++) {
            int arow = aoff + wm + mt * 16 + b3 * 8 + l7;
            uint32_t off = arow * 128 + colb + b4 * 16;
            uint32_t ah[4], al[4];
            ldm_x4(ah, Ab + SWZ(off));
            ldm_x4(al, Ab + SWZ(off + 64));
            #pragma unroll
            for (int bt = 0; bt < NBT; bt++) {
                mma_bf16(acc[mt][bt], ah, bh[bt]);
                mma_bf16(acc[mt][bt], ah, bl[bt]);
                mma_bf16(acc[mt][bt], al, bh[bt]);
            }
        }
    }
}

// ---------------- hats GEMM (fp32 A direct) + fused segmax/act/state_seq -----
// grid (2, GRP): blockIdx.y = group (128 rows), blockIdx.x = 128-col slice.
// A is read fp32 from NEs and split in-kernel (no split_arr pass).
#define G128_STAGE 32768u
#define G128_DYN   (2 * 32768 + 1024)
__global__ __launch_bounds__(256, 2)
void hats_gemm(const float* __restrict__ NEs,
               const bf16* __restrict__ Wgh, const bf16* __restrict__ Wgl,
               const float* __restrict__ bias,
               const float* __restrict__ nodes, const int* __restrict__ act,
               bf16* __restrict__ Ch, bf16* __restrict__ Cl,
               float* __restrict__ HAts, float* __restrict__ seqf,
               bf16* __restrict__ seqh, bf16* __restrict__ seql)
{
    extern __shared__ char dyn[];
    __shared__ float smax[4][128];
    uint32_t sbase = (smem_u32(dyn) + 1023u) & ~1023u;
    int tid = threadIdx.x, lane = tid & 31, w = tid >> 5;
    int wm = (w & 3) * 32, wn = (w >> 2) * 64;
    int g = blockIdx.y;
    int row0 = g * 128, col0 = blockIdx.x * 128;
    const int nch = 8;   // K = 256

    // A: LDG fp32 -> split -> STS into [32 hi | 32 lo] swizzled rows
    auto ldsts_A = [&](int c, int s) {
        int k0 = c * KCH;
        uint32_t Ab = sbase + (uint32_t)s * G128_STAGE;
        #pragma unroll
        for (int t = 0; t < 4; t++) {
            int idx = tid + t * 256;
            int row = idx >> 3, seg = idx & 7;
            float4 f = *(const float4*)(NEs + (size_t)(row0 + row) * 256 + k0 + seg * 4);
            bf16 h0, l0, h1, l1, h2, l2, h3, l3;
            split2(f.x, h0, l0); split2(f.y, h1, l1);
            split2(f.z, h2, l2); split2(f.w, h3, l3);
            __nv_bfloat162 hp0 = {h0, h1}, hp1 = {h2, h3};
            __nv_bfloat162 lp0 = {l0, l1}, lp1 = {l2, l3};
            uint32_t ho = SWZ((uint32_t)(row * 128 + seg * 8));
            uint32_t lo = SWZ((uint32_t)(row * 128 + 64 + seg * 8));
            asm volatile("st.shared.v2.b32 [%0], {%1,%2};" :: "r"(Ab + ho),
                "r"(*(uint32_t*)&hp0), "r"(*(uint32_t*)&hp1) : "memory");
            asm volatile("st.shared.v2.b32 [%0], {%1,%2};" :: "r"(Ab + lo),
                "r"(*(uint32_t*)&lp0), "r"(*(uint32_t*)&lp1) : "memory");
        }
    };
    auto load_B = [&](int c, int s) {
        int k0 = c * KCH;
        uint32_t Bb = sbase + (uint32_t)s * G128_STAGE + 16384u;
        #pragma unroll
        for (int t = 0; t < 4; t++) {
            int idx = tid + t * 256;
            int row = idx >> 3, sub = idx & 7, half = sub >> 2, q = sub & 3;
            const bf16* src = (half ? Wgl : Wgh) + (size_t)(col0 + row) * 256 + k0 + q * 8;
            CP16(Bb + SWZ(row * 128 + half * 64 + q * 16), src, 1);
        }
    };

    float acc[2][8][4] = {};
    load_B(0, 0); CP_COMMIT();
    load_B(1, 1); CP_COMMIT();
    ldsts_A(0, 0);
    for (int c = 0; c < nch; c++) {
        if (c + 1 < nch) { CP_WAIT1(); } else { CP_WAIT0(); }
        __syncthreads();
        // stage A for next chunk into the other buffer (its old A is consumed)
        if (c + 1 < nch) ldsts_A(c + 1, (c + 1) & 1);
        uint32_t Ab = sbase + (uint32_t)(c & 1) * G128_STAGE;
        compute_chunk_t<8>(Ab, Ab + 16384u, 0, wm, wn, lane, acc);
        __syncthreads();
        if (c + 2 < nch) { load_B(c + 2, c & 1); CP_COMMIT(); }
    }

    // ---- epilogue: hats hi/lo + col-max + act-row gather ----
    int ra = (g < GRP - 1) ? act[g] : -1;
    float cmax[16];
    #pragma unroll
    for (int i = 0; i < 16; i++) cmax[i] = 0.f;   // relu outputs >= 0

    #pragma unroll
    for (int mt = 0; mt < 2; mt++) {
        #pragma unroll
        for (int ih = 0; ih < 2; ih++) {
            int rl = wm + mt * 16 + ih * 8 + (lane >> 2);
            #pragma unroll
            for (int bt = 0; bt < 8; bt++) {
                int ccl = wn + bt * 8 + (lane & 3) * 2;
                int cc = col0 + ccl;
                float v0 = fmaxf(acc[mt][bt][ih * 2 + 0] + bias[cc], 0.f);
                float v1 = fmaxf(acc[mt][bt][ih * 2 + 1] + bias[cc + 1], 0.f);
                size_t idx = (size_t)(row0 + rl) * 256 + cc;
                bf16 h0, l0, h1, l1;
                split2(v0, h0, l0); split2(v1, h1, l1);
                __nv_bfloat162 hp = {h0, h1}, lp = {l0, l1};
                *(__nv_bfloat162*)(Ch + idx) = hp;
                *(__nv_bfloat162*)(Cl + idx) = lp;
                cmax[bt * 2]     = fmaxf(cmax[bt * 2], v0);
                cmax[bt * 2 + 1] = fmaxf(cmax[bt * 2 + 1], v1);
                if (rl == ra) {
                    size_t sid = (size_t)(3 * g + 2) * 256 + cc;
                    *(float2*)(seqf + sid) = make_float2(v0, v1);
                    *(__nv_bfloat162*)(seqh + sid) = hp;
                    *(__nv_bfloat162*)(seql + sid) = lp;
                }
            }
        }
    }
    #pragma unroll
    for (int i = 0; i < 16; i++) {
        float m = cmax[i];
        m = fmaxf(m, __shfl_xor_sync(0xffffffffu, m, 4));
        m = fmaxf(m, __shfl_xor_sync(0xffffffffu, m, 8));
        m = fmaxf(m, __shfl_xor_sync(0xffffffffu, m, 16));
        cmax[i] = m;
    }
    if ((lane >> 2) == 0) {
        #pragma unroll
        for (int bt = 0; bt < 8; bt++) {
            int ccl = wn + bt * 8 + lane * 2;
            smax[w & 3][ccl]     = cmax[bt * 2];
            smax[w & 3][ccl + 1] = cmax[bt * 2 + 1];
        }
    }
    __syncthreads();
    if (tid < 128) {
        int cc = col0 + tid;
        float m = fmaxf(fmaxf(smax[0][tid], smax[1][tid]),
                        fmaxf(smax[2][tid], smax[3][tid]));
        HAts[g * 256 + cc] = m;
        bf16 a, b;
        float nv = nodes[g * 256 + cc];
        if (g < GRP - 1) {
            size_t sid = (size_t)(3 * g + 1) * 256 + cc;
            seqf[sid] = m;
            split2(m, a, b); seqh[sid] = a; seql[sid] = b;
            sid = (size_t)(3 * g) * 256 + cc;
            seqf[sid] = nv;
            split2(nv, a, b); seqh[sid] = a; seql[sid] = b;
        } else {
            size_t sid = (size_t)(SEQL - 1) * 256 + cc;
            seqf[sid] = nv;
            split2(nv, a, b); seqh[sid] = a; seql[sid] = b;
        }
    }
}

// ---------------- TCN with halo (dynamic stage size) -------------------------
template<int DUAL>
__global__ __launch_bounds__(128, 3)
void tcn64(const bf16* __restrict__ Agh, const bf16* __restrict__ Agl,
           const bf16* __restrict__ Wgh, const bf16* __restrict__ Wgl,
           const bf16* __restrict__ Wdh, const bf16* __restrict__ Wdl,
           const float* __restrict__ bias, const float* __restrict__ Rf,
           float* __restrict__ Cf, bf16* __restrict__ Ch, bf16* __restrict__ Cl,
           int Mv, int N, int K, int npass, int dil, int doRelu)
{
    extern __shared__ char dyn[];
    uint32_t sbase = (smem_u32(dyn) + 1023u) & ~1023u;
    int tid = threadIdx.x, lane = tid & 31, w = tid >> 5;
    int wm = (w & 1) * 32, wn = (w >> 1) * 32;
    int row0 = blockIdx.y * 64, col0 = blockIdx.x * 64;
    int halo = (npass >= 3) ? 2 * dil : 0;
    int nrows = 64 + halo;
    uint32_t Abytes = (uint32_t)nrows * 128u;
    uint32_t stage = (Abytes + (uint32_t)npass * 8192u + 1023u) & ~1023u;
    int nch = K / KCH;

    auto load_stage = [&](int c, int s) {
        int k0 = c * KCH;
        uint32_t Ab = sbase + (uint32_t)s * stage;
        for (int idx = tid; idx < nrows * 8; idx += 128) {
            int row = idx >> 3, sub = idx & 7, half = sub >> 2, q = sub & 3;
            int ga = row0 - halo + row;
            const bf16* src = (half ? Agl : Agh)
                              + (size_t)(ga < 0 ? 0 : ga) * K + k0 + q * 8;
            CP16(Ab + SWZ(row * 128 + half * 64 + q * 16), src, ga >= 0);
        }
        for (int p = 0; p < npass; p++) {
            const bf16* Ph = (p < 3) ? Wgh + (size_t)p * N * K : Wdh;
            const bf16* Pl = (p < 3) ? Wgl + (size_t)p * N * K : Wdl;
            uint32_t Bb = Ab + Abytes + (uint32_t)p * 8192u;
            #pragma unroll
            for (int t = 0; t < 4; t++) {
                int idx = tid + t * 128;
                int row = idx >> 3, sub = idx & 7, half = sub >> 2, q = sub & 3;
                const bf16* src = (half ? Pl : Ph) + (size_t)(col0 + row) * K + k0 + q * 8;
                CP16(Bb + SWZ(row * 128 + half * 64 + q * 16), src, 1);
            }
        }
    };

    float acc[2][4][4] = {};
    float accR[DUAL ? 2 : 1][DUAL ? 4 : 1][DUAL ? 4 : 1] = {};
    load_stage(0, 0); CP_COMMIT();
    if (nch > 1) { load_stage(1, 1); CP_COMMIT(); }
    for (int c = 0; c < nch; c++) {
        if (c + 1 < nch) { CP_WAIT1(); } else { CP_WAIT0(); }
        __syncthreads();
        uint32_t Ab = sbase + (uint32_t)(c & 1) * stage;
        for (int p = 0; p < npass; p++) {
            int aoff = (p < 3) ? p * dil : 2 * dil;
            uint32_t Bb = Ab + Abytes + (uint32_t)p * 8192u;
            if (DUAL && p == 3)
                compute_chunk_t<4>(Ab, Bb, aoff, wm, wn, lane, (float (*)[4][4])accR);
            else
                compute_chunk_t<4>(Ab, Bb, aoff, wm, wn, lane, acc);
        }
        __syncthreads();
        if (c + 2 < nch) { load_stage(c + 2, c & 1); CP_COMMIT(); }
    }

    #pragma unroll
    for (int mt = 0; mt < 2; mt++) {
        #pragma unroll
        for (int ih = 0; ih < 2; ih++) {
            int rr = row0 + wm + mt * 16 + ih * 8 + (lane >> 2);
            if (rr >= Mv) continue;
            #pragma unroll
            for (int bt = 0; bt < 4; bt++) {
                int cc = col0 + wn + bt * 8 + (lane & 3) * 2;
                size_t idx = (size_t)rr * N + cc;
                float v0 = acc[mt][bt][ih * 2 + 0] + bias[cc];
                float v1 = acc[mt][bt][ih * 2 + 1] + bias[cc + 1];
                if (doRelu) { v0 = fmaxf(v0, 0.f); v1 = fmaxf(v1, 0.f); }
                if (DUAL) {
                    v0 = fmaxf(v0 + accR[mt][bt][ih * 2 + 0], 0.f);
                    v1 = fmaxf(v1 + accR[mt][bt][ih * 2 + 1], 0.f);
                } else if (Rf) {
                    float2 rv = *(const float2*)(Rf + idx);
                    v0 = fmaxf(v0 + rv.x, 0.f);
                    v1 = fmaxf(v1 + rv.y, 0.f);
                }
                if (Cf) *(float2*)(Cf + idx) = make_float2(v0, v1);
                if (Ch) {
                    bf16 h0, l0, h1, l1;
                    split2(v0, h0, l0); split2(v1, h1, l1);
                    __nv_bfloat162 hp = {h0, h1}, lp = {l0, l1};
                    *(__nv_bfloat162*)(Ch + idx) = hp;
                    *(__nv_bfloat162*)(Cl + idx) = lp;
                }
            }
        }
    }
}

static int tcn_dyn(int npass, int dil) {
    int halo = (npass >= 3) ? 2 * dil : 0;
    unsigned Abytes = (unsigned)(64 + halo) * 128u;
    unsigned stage = (Abytes + (unsigned)npass * 8192u + 1023u) & ~1023u;
    return (int)(2 * stage + 1024);
}

// ---------------- fused final: out = relu(hats@Wp1bot + GT[g]) @ Wp2 + bp2 --
// block tile 128x128 (NBT=8): 4 n-tiles x 8 k-chunks = 32 chunks; A re-read 4x.
#define FIN_STAGE 32768u
#define FIN_DYN   (2 * 32768 + 1024)
__global__ __launch_bounds__(256, 2)
void final_mma(const bf16* __restrict__ Hh, const bf16* __restrict__ Hl,
               const bf16* __restrict__ Bgh, const bf16* __restrict__ Bgl,
               const float* __restrict__ GT, const float* __restrict__ W2,
               const float* __restrict__ bp2, float* __restrict__ out)
{
    extern __shared__ char dyn[];
    __shared__ float sGT[512], sW2[512], sred[128][2];
    uint32_t sbase = (smem_u32(dyn) + 1023u) & ~1023u;
    int g = blockIdx.x;
    int tid = threadIdx.x, lane = tid & 31, w = tid >> 5;
    int wm = (w & 3) * 32, wn = (w >> 2) * 64;

    for (int i = tid; i < 512; i += 256) {
        sGT[i] = GT[(size_t)g * 512 + i];
        sW2[i] = W2[i];
    }

    const bf16* Ah = Hh + (size_t)g * PER * DIM;
    const bf16* Al = Hl + (size_t)g * PER * DIM;

    auto load_stage = [&](int c, int s) {
        int nt = c >> 3;
        int k0 = (c & 7) * KCH;
        uint32_t Ab = sbase + (uint32_t)s * FIN_STAGE;
        uint32_t Bb = Ab + 16384u;
        #pragma unroll
        for (int t = 0; t < 4; t++) {
            int idx = tid + t * 256;
            int row = idx >> 3, sub = idx & 7, half = sub >> 2, q = sub & 3;
            const bf16* src = (half ? Al : Ah) + (size_t)row * DIM + k0 + q * 8;
            CP16(Ab + SWZ(row * 128 + half * 64 + q * 16), src, 1);
        }
        #pragma unroll
        for (int t = 0; t < 4; t++) {
            int idx = tid + t * 256;
            int row = idx >> 3, sub = idx & 7, half = sub >> 2, q = sub & 3;
            const bf16* src = (half ? Bgl : Bgh)
                              + (size_t)(nt * 128 + row) * DIM + k0 + q * 8;
            CP16(Bb + SWZ(row * 128 + half * 64 + q * 16), src, 1);
        }
    };

    float acc[2][8][4] = {};
    float qsum[4] = {};
    const int nch = 32;
    load_stage(0, 0); CP_COMMIT();
    load_stage(1, 1); CP_COMMIT();
    for (int c = 0; c < nch; c++) {
        if (c + 1 < nch) { CP_WAIT1(); } else { CP_WAIT0(); }
        __syncthreads();
        uint32_t Ab = sbase + (uint32_t)(c & 1) * FIN_STAGE;
        compute_chunk_t<8>(Ab, Ab + 16384u, 0, wm, wn, lane, acc);
        __syncthreads();
        if (c + 2 < nch) { load_stage(c + 2, c & 1); CP_COMMIT(); }
        if ((c & 7) == 7) {
            int nt = c >> 3;
            #pragma unroll
            for (int mt = 0; mt < 2; mt++) {
                #pragma unroll
                for (int bt = 0; bt < 8; bt++) {
                    #pragma unroll
                    for (int i = 0; i < 4; i++) {
                        int cc = nt * 128 + wn + bt * 8 + (lane & 3) * 2 + (i & 1);
                        float hv = fmaxf(acc[mt][bt][i] + sGT[cc], 0.f);
                        qsum[mt * 2 + (i >> 1)] += hv * sW2[cc];
                        acc[mt][bt][i] = 0.f;
                    }
                }
            }
        }
    }

    #pragma unroll
    for (int mt = 0; mt < 2; mt++) {
        #pragma unroll
        for (int ih = 0; ih < 2; ih++) {
            float v = qsum[mt * 2 + ih];
            v += __shfl_xor_sync(0xffffffffu, v, 1);
            v += __shfl_xor_sync(0xffffffffu, v, 2);
            if ((lane & 3) == 0)
                sred[wm + mt * 16 + ih * 8 + (lane >> 2)][w >> 2] = v;
        }
    }
    __syncthreads();
    if (tid < 128)
        out[(size_t)g * PER + tid] = sred[tid][0] + sred[tid][1] + bp2[0];
}

// ---------------- build state_HS = [query | hs | HAts] (hi/lo) --------------
__global__ void build_sHS(const float* __restrict__ query, const float* __restrict__ xf,
                          const float* __restrict__ HAts, bf16* __restrict__ h,
                          bf16* __restrict__ l)
{
    int g = blockIdx.x, c = threadIdx.x;
    bf16 a, b;
    split2(query[g * DIM + c], a, b);
    h[g * 768 + c] = a; l[g * 768 + c] = b;
    split2(xf[(size_t)(3 * g) * DIM + c], a, b);
    h[g * 768 + 256 + c] = a; l[g * 768 + 256 + c] = b;
    split2(HAts[g * DIM + c], a, b);
    h[g * 768 + 512 + c] = a; l[g * 768 + 512 + c] = b;
}

// ---------------- launcher --------------------------------------------------
extern "C" void kernel_launch(void* const* d_in, const int* in_sizes, int n_in,
                              void* d_out, int out_size)
{
    const float* NEs   = (const float*)d_in[0];
    const float* nodes = (const float*)d_in[1];
    const float* query = (const float*)d_in[2];
    const int*   act   = (const int*)d_in[4];
    const float* Wa    = (const float*)d_in[5];
    const float* ba    = (const float*)d_in[6];
    const float* Wc0   = (const float*)d_in[7];
    const float* bc0   = (const float*)d_in[8];
    const float* Wc1   = (const float*)d_in[9];
    const float* bc1   = (const float*)d_in[10];
    const float* Wd1   = (const float*)d_in[11];
    const float* Wc2   = (const float*)d_in[12];
    const float* bc2   = (const float*)d_in[13];
    const float* Wc3   = (const float*)d_in[14];
    const float* bc3   = (const float*)d_in[15];
    const float* Wd3   = (const float*)d_in[16];
    const float* Wp1   = (const float*)d_in[17];
    const float* bp1   = (const float*)d_in[18];
    const float* Wp2   = (const float*)d_in[19];
    const float* bp2   = (const float*)d_in[20];
    float* out = (float*)d_out;

    int tcn_max = tcn_dyn(4, 8);
    cudaFuncSetAttribute(hats_gemm, cudaFuncAttributeMaxDynamicSharedMemorySize, G128_DYN);
    cudaFuncSetAttribute(tcn64<0>,  cudaFuncAttributeMaxDynamicSharedMemorySize, tcn_max);
    cudaFuncSetAttribute(tcn64<1>,  cudaFuncAttributeMaxDynamicSharedMemorySize, tcn_max);
    cudaFuncSetAttribute(final_mma, cudaFuncAttributeMaxDynamicSharedMemorySize, FIN_DYN);

    bf16 *hh, *hl, *seqh, *seql, *x1h, *x1l, *x2h, *x2l;
    bf16 *wah, *wal, *wc0h, *wc0l, *wc1h, *wc1l, *wc2h, *wc2l, *wc3h, *wc3l;
    bf16 *wd1h, *wd1l, *wd3h, *wd3l, *wp1th, *wp1tl, *wp1bh, *wp1bl, *sHSh, *sHSl;
    float *HAts, *seqf, *x2f, *GT;
    cudaGetSymbolAddress((void**)&hh,   g_hh);    cudaGetSymbolAddress((void**)&hl,   g_hl);
    cudaGetSymbolAddress((void**)&HAts, g_HAts);
    cudaGetSymbolAddress((void**)&seqf, g_seqf);
    cudaGetSymbolAddress((void**)&seqh, g_seqh);  cudaGetSymbolAddress((void**)&seql, g_seql);
    cudaGetSymbolAddress((void**)&x1h,  g_x1h);   cudaGetSymbolAddress((void**)&x1l,  g_x1l);
    cudaGetSymbolAddress((void**)&x2f,  g_x2f);
    cudaGetSymbolAddress((void**)&x2h,  g_x2h);   cudaGetSymbolAddress((void**)&x2l,  g_x2l);
    cudaGetSymbolAddress((void**)&wah,  g_wah);   cudaGetSymbolAddress((void**)&wal,  g_wal);
    cudaGetSymbolAddress((void**)&wc0h, g_wc0h);  cudaGetSymbolAddress((void**)&wc0l, g_wc0l);
    cudaGetSymbolAddress((void**)&wc1h, g_wc1h);  cudaGetSymbolAddress((void**)&wc1l, g_wc1l);
    cudaGetSymbolAddress((void**)&wc2h, g_wc2h);  cudaGetSymbolAddress((void**)&wc2l, g_wc2l);
    cudaGetSymbolAddress((void**)&wc3h, g_wc3h);  cudaGetSymbolAddress((void**)&wc3l, g_wc3l);
    cudaGetSymbolAddress((void**)&wd1h, g_wd1h);  cudaGetSymbolAddress((void**)&wd1l, g_wd1l);
    cudaGetSymbolAddress((void**)&wd3h, g_wd3h);  cudaGetSymbolAddress((void**)&wd3l, g_wd3l);
    cudaGetSymbolAddress((void**)&wp1th, g_wp1th); cudaGetSymbolAddress((void**)&wp1tl, g_wp1tl);
    cudaGetSymbolAddress((void**)&wp1bh, g_wp1bh); cudaGetSymbolAddress((void**)&wp1bl, g_wp1bl);
    cudaGetSymbolAddress((void**)&sHSh, g_sHSh);  cudaGetSymbolAddress((void**)&sHSl, g_sHSl);
    cudaGetSymbolAddress((void**)&GT,   g_GT);

    // 0) weight prep
    split_weights<<<SPLITW_BLOCKS, 256>>>(Wa, Wc0, Wc1, Wc2, Wc3, Wd1, Wd3, Wp1,
        wah, wal, wc0h, wc0l, wc1h, wc1l, wc2h, wc2l, wc3h, wc3l,
        wd1h, wd1l, wd3h, wd3l, wp1th, wp1tl, wp1bh, wp1bl);

    // 1) hats GEMM (fp32 A direct) + fused segmax/act/state_seq
    hats_gemm<<<dim3(2, GRP), 256, G128_DYN>>>(NEs, wah, wal, ba,
        nodes, act, hh, hl, HAts, seqf, seqh, seql);

    // 2) TCN (launches 2-5)
    tcn64<0><<<dim3(4, 24), 128, tcn_dyn(3, 1)>>>(seqh, seql, wc0h, wc0l,
        nullptr, nullptr, bc0, seqf, nullptr, x1h, x1l, SEQL, 256, 256, 3, 1, 1);
    tcn64<1><<<dim3(8, 24), 128, tcn_dyn(4, 2)>>>(x1h, x1l, wc1h, wc1l,
        wd1h, wd1l, bc1, nullptr, x2f, x2h, x2l, SEQL, 512, 256, 4, 2, 1);
    tcn64<0><<<dim3(8, 24), 128, tcn_dyn(3, 4)>>>(x2h, x2l, wc2h, wc2l,
        nullptr, nullptr, bc2, x2f, nullptr, x1h, x1l, SEQL, 512, 512, 3, 4, 1);
    tcn64<1><<<dim3(4, 24), 128, tcn_dyn(4, 8)>>>(x1h, x1l, wc3h, wc3l,
        wd3h, wd3l, bc3, nullptr, x2f, nullptr, nullptr, SEQL, 256, 512, 4, 8, 1);

    // 3) state_HS and group term GT = sHS @ Wp1top + bp1
    build_sHS<<<GRP, DIM>>>(query, x2f, HAts, sHSh, sHSl);
    tcn64<0><<<dim3(8, 8), 128, tcn_dyn(1, 0)>>>(sHSh, sHSl, wp1th, wp1tl,
        nullptr, nullptr, bp1, nullptr, GT, nullptr, nullptr, GRP, HID, 768, 1, 0, 0);

    // 4) fused final GEMM + Wp2 reduction (128x128 tiles)
    final_mma<<<GRP, 256, FIN_DYN>>>(hh, hl, wp1bh, wp1bl, GT, Wp2, bp2, out);
}

// round 13
// speedup vs baseline: 1.5987x; 1.0036x over previous
#include <cuda_runtime.h>
#include <cuda_bf16.h>
#include <cstdint>

#define N_TOT 65536
#define GRP   512
#define PER   128
#define DIM   256
#define SEQL  1534
#define HID   512
#define KCH   32

typedef __nv_bfloat16 bf16;

// ---------------- scratch (device globals; no allocation allowed) ----------
__device__ bf16  g_hh  [N_TOT * DIM];
__device__ bf16  g_hl  [N_TOT * DIM];
__device__ float g_HAts[GRP * DIM];
__device__ float g_seqf[1536 * DIM];
__device__ bf16  g_seqh[1536 * DIM];
__device__ bf16  g_seql[1536 * DIM];
__device__ bf16  g_x1h [1536 * 512];
__device__ bf16  g_x1l [1536 * 512];
__device__ float g_x2f [1536 * 512];
__device__ bf16  g_x2h [1536 * 512];
__device__ bf16  g_x2l [1536 * 512];
__device__ bf16  g_wah [DIM * DIM];
__device__ bf16  g_wal [DIM * DIM];
__device__ bf16  g_wc0h[3 * 256 * 256];
__device__ bf16  g_wc0l[3 * 256 * 256];
__device__ bf16  g_wc1h[3 * 512 * 256];
__device__ bf16  g_wc1l[3 * 512 * 256];
__device__ bf16  g_wc2h[3 * 512 * 512];
__device__ bf16  g_wc2l[3 * 512 * 512];
__device__ bf16  g_wc3h[3 * 256 * 512];
__device__ bf16  g_wc3l[3 * 256 * 512];
__device__ bf16  g_wd1h[512 * 256];
__device__ bf16  g_wd1l[512 * 256];
__device__ bf16  g_wd3h[256 * 512];
__device__ bf16  g_wd3l[256 * 512];
__device__ bf16  g_wp1th[512 * 768];
__device__ bf16  g_wp1tl[512 * 768];
__device__ bf16  g_wp1bh[512 * 256];
__device__ bf16  g_wp1bl[512 * 256];
__device__ bf16  g_sHSh[GRP * 768];
__device__ bf16  g_sHSl[GRP * 768];
__device__ float g_GT  [GRP * 512];

// ---------------- low-level helpers -----------------------------------------
__device__ __forceinline__ uint32_t smem_u32(const void* p) {
    uint32_t a;
    asm("{ .reg .u64 t; cvta.to.shared.u64 t, %1; cvt.u32.u64 %0, t; }"
        : "=r"(a) : "l"(p));
    return a;
}
static __device__ __forceinline__ uint32_t SWZ(uint32_t off) {
    return off ^ ((off >> 3) & 0x70);
}
__device__ __forceinline__ void mma_bf16(float* c, const uint32_t* a, const uint32_t* b) {
    asm volatile(
        "mma.sync.aligned.m16n8k16.row.col.f32.bf16.bf16.f32 "
        "{%0,%1,%2,%3}, {%4,%5,%6,%7}, {%8,%9}, {%0,%1,%2,%3};\n"
        : "+f"(c[0]), "+f"(c[1]), "+f"(c[2]), "+f"(c[3])
        : "r"(a[0]), "r"(a[1]), "r"(a[2]), "r"(a[3]), "r"(b[0]), "r"(b[1]));
}
__device__ __forceinline__ void ldm_x4(uint32_t* r, uint32_t a) {
    asm volatile("ldmatrix.sync.aligned.m8n8.x4.shared.b16 {%0,%1,%2,%3}, [%4];"
        : "=r"(r[0]), "=r"(r[1]), "=r"(r[2]), "=r"(r[3]) : "r"(a));
}
#define CP16(dst, src, pred) do {                                              \
    int _sz = (pred) ? 16 : 0;                                                 \
    asm volatile("cp.async.cg.shared.global [%0], [%1], 16, %2;"               \
        :: "r"(dst), "l"(src), "r"(_sz) : "memory"); } while (0)
#define CP_COMMIT() asm volatile("cp.async.commit_group;" ::: "memory")
#define CP_WAIT1()  asm volatile("cp.async.wait_group 1;" ::: "memory")
#define CP_WAIT0()  asm volatile("cp.async.wait_group 0;" ::: "memory")

// ---------------- split helpers ---------------------------------------------
__device__ __forceinline__ void split2(float v, bf16& h, bf16& l) {
    h = __float2bfloat16(v);
    l = __float2bfloat16(v - __bfloat162float(h));
}
__device__ __forceinline__ void d_tsplit(const float* w, bf16* h, bf16* l,
                                         int K, int N, int i)
{
    if (i < K * N) {
        int k = i / N, n = i % N;
        bf16 a, b; split2(w[i], a, b);
        h[(size_t)n * K + k] = a;
        l[(size_t)n * K + k] = b;
    }
}
__device__ __forceinline__ void d_conv(const float* w, bf16* h, bf16* l,
                                       int Cout, int Cin, int i)
{
    if (i < Cout * Cin * 3) {
        int j  = i % 3;
        int ci = (i / 3) % Cin;
        int co = i / (3 * Cin);
        bf16 a, b; split2(w[i], a, b);
        size_t d = ((size_t)j * Cout + co) * Cin + ci;
        h[d] = a; l[d] = b;
    }
}
__device__ __forceinline__ void d_arr(const float* w, bf16* h, bf16* l, int n, int i)
{
    if (i < n) { bf16 a, b; split2(w[i], a, b); h[i] = a; l[i] = b; }
}

__global__ void split_weights(
    const float* Wa, const float* Wc0, const float* Wc1, const float* Wc2,
    const float* Wc3, const float* Wd1, const float* Wd3, const float* Wp1,
    bf16* wah, bf16* wal, bf16* wc0h, bf16* wc0l, bf16* wc1h, bf16* wc1l,
    bf16* wc2h, bf16* wc2l, bf16* wc3h, bf16* wc3l, bf16* wd1h, bf16* wd1l,
    bf16* wd3h, bf16* wd3l, bf16* wp1th, bf16* wp1tl, bf16* wp1bh, bf16* wp1bl)
{
    int b = blockIdx.x, t = threadIdx.x;
    if (b < 256)        { d_tsplit(Wa, wah, wal, 256, 256, b * 256 + t); return; }
    b -= 256;
    if (b < 768)        { d_conv(Wc0, wc0h, wc0l, 256, 256, b * 256 + t); return; }
    b -= 768;
    if (b < 1536)       { d_conv(Wc1, wc1h, wc1l, 512, 256, b * 256 + t); return; }
    b -= 1536;
    if (b < 3072)       { d_conv(Wc2, wc2h, wc2l, 512, 512, b * 256 + t); return; }
    b -= 3072;
    if (b < 1536)       { d_conv(Wc3, wc3h, wc3l, 256, 512, b * 256 + t); return; }
    b -= 1536;
    if (b < 512)        { d_arr(Wd1, wd1h, wd1l, 512 * 256, b * 256 + t); return; }
    b -= 512;
    if (b < 512)        { d_arr(Wd3, wd3h, wd3l, 256 * 512, b * 256 + t); return; }
    b -= 512;
    if (b < 1536)       { d_tsplit(Wp1, wp1th, wp1tl, 768, 512, b * 256 + t); return; }
    b -= 1536;
    if (b < 512)        { d_tsplit(Wp1 + 768 * 512, wp1bh, wp1bl, 256, 512, b * 256 + t); }
}
#define SPLITW_BLOCKS (256 + 768 + 1536 + 3072 + 1536 + 512 + 512 + 1536 + 512)

// ---------------- warp compute for one k32 chunk -----------------------------
// warp tile = MT*16 (m) x NBT*8 (n)
template<int MT, int NBT>
__device__ __forceinline__ void compute_chunk_t(uint32_t Ab, uint32_t Bb, int aoff,
                                                int wm, int wn, int lane,
                                                float acc[MT][NBT][4])
{
    int l7 = lane & 7;
    int b3 = (lane >> 3) & 1;
    int b4 = (lane >> 4) & 1;
    #pragma unroll
    for (int ks = 0; ks < 2; ks++) {
        int colb = ks * 32;
        uint32_t bh[NBT][2], bl[NBT][2];
        #pragma unroll
        for (int pp = 0; pp < NBT / 2; pp++) {
            int nrow = wn + pp * 16 + b4 * 8 + l7;
            uint32_t off = nrow * 128 + colb + b3 * 16;
            uint32_t rh[4], rl[4];
            ldm_x4(rh, Bb + SWZ(off));
            ldm_x4(rl, Bb + SWZ(off + 64));
            bh[pp * 2 + 0][0] = rh[0]; bh[pp * 2 + 0][1] = rh[1];
            bh[pp * 2 + 1][0] = rh[2]; bh[pp * 2 + 1][1] = rh[3];
            bl[pp * 2 + 0][0] = rl[0]; bl[pp * 2 + 0][1] = rl[1];
            bl[pp * 2 + 1][0] = rl[2]; bl[pp * 2 + 1][1] = rl[3];
        }
        #pragma unroll
        for (int mt = 0; mt < MT; mt++) {
            int arow = aoff + wm + mt * 16 + b3 * 8 + l7;
            uint32_t off = arow * 128 + colb + b4 * 16;
            uint32_t ah[4], al[4];
            ldm_x4(ah, Ab + SWZ(off));
            ldm_x4(al, Ab + SWZ(off + 64));
            #pragma unroll
            for (int bt = 0; bt < NBT; bt++) {
                mma_bf16(acc[mt][bt], ah, bh[bt]);
                mma_bf16(acc[mt][bt], ah, bl[bt]);
                mma_bf16(acc[mt][bt], al, bh[bt]);
            }
        }
    }
}

// ---------------- hats GEMM (fp32 A direct) + fused segmax/act/state_seq -----
// grid (2, GRP): blockIdx.y = group (128 rows), blockIdx.x = 128-col slice.
#define G128_STAGE 32768u
#define G128_DYN   (2 * 32768 + 1024)
__global__ __launch_bounds__(256, 2)
void hats_gemm(const float* __restrict__ NEs,
               const bf16* __restrict__ Wgh, const bf16* __restrict__ Wgl,
               const float* __restrict__ bias,
               const float* __restrict__ nodes, const int* __restrict__ act,
               bf16* __restrict__ Ch, bf16* __restrict__ Cl,
               float* __restrict__ HAts, float* __restrict__ seqf,
               bf16* __restrict__ seqh, bf16* __restrict__ seql)
{
    extern __shared__ char dyn[];
    __shared__ float smax[4][128];
    uint32_t sbase = (smem_u32(dyn) + 1023u) & ~1023u;
    int tid = threadIdx.x, lane = tid & 31, w = tid >> 5;
    int wm = (w & 3) * 32, wn = (w >> 2) * 64;
    int g = blockIdx.y;
    int row0 = g * 128, col0 = blockIdx.x * 128;
    const int nch = 8;   // K = 256

    auto ldsts_A = [&](int c, int s) {
        int k0 = c * KCH;
        uint32_t Ab = sbase + (uint32_t)s * G128_STAGE;
        #pragma unroll
        for (int t = 0; t < 4; t++) {
            int idx = tid + t * 256;
            int row = idx >> 3, seg = idx & 7;
            float4 f = *(const float4*)(NEs + (size_t)(row0 + row) * 256 + k0 + seg * 4);
            bf16 h0, l0, h1, l1, h2, l2, h3, l3;
            split2(f.x, h0, l0); split2(f.y, h1, l1);
            split2(f.z, h2, l2); split2(f.w, h3, l3);
            __nv_bfloat162 hp0 = {h0, h1}, hp1 = {h2, h3};
            __nv_bfloat162 lp0 = {l0, l1}, lp1 = {l2, l3};
            uint32_t ho = SWZ((uint32_t)(row * 128 + seg * 8));
            uint32_t lo = SWZ((uint32_t)(row * 128 + 64 + seg * 8));
            asm volatile("st.shared.v2.b32 [%0], {%1,%2};" :: "r"(Ab + ho),
                "r"(*(uint32_t*)&hp0), "r"(*(uint32_t*)&hp1) : "memory");
            asm volatile("st.shared.v2.b32 [%0], {%1,%2};" :: "r"(Ab + lo),
                "r"(*(uint32_t*)&lp0), "r"(*(uint32_t*)&lp1) : "memory");
        }
    };
    auto load_B = [&](int c, int s) {
        int k0 = c * KCH;
        uint32_t Bb = sbase + (uint32_t)s * G128_STAGE + 16384u;
        #pragma unroll
        for (int t = 0; t < 4; t++) {
            int idx = tid + t * 256;
            int row = idx >> 3, sub = idx & 7, half = sub >> 2, q = sub & 3;
            const bf16* src = (half ? Wgl : Wgh) + (size_t)(col0 + row) * 256 + k0 + q * 8;
            CP16(Bb + SWZ(row * 128 + half * 64 + q * 16), src, 1);
        }
    };

    float acc[2][8][4] = {};
    load_B(0, 0); CP_COMMIT();
    load_B(1, 1); CP_COMMIT();
    ldsts_A(0, 0);
    for (int c = 0; c < nch; c++) {
        if (c + 1 < nch) { CP_WAIT1(); } else { CP_WAIT0(); }
        __syncthreads();
        if (c + 1 < nch) ldsts_A(c + 1, (c + 1) & 1);
        uint32_t Ab = sbase + (uint32_t)(c & 1) * G128_STAGE;
        compute_chunk_t<2, 8>(Ab, Ab + 16384u, 0, wm, wn, lane, acc);
        __syncthreads();
        if (c + 2 < nch) { load_B(c + 2, c & 1); CP_COMMIT(); }
    }

    int ra = (g < GRP - 1) ? act[g] : -1;
    float cmax[16];
    #pragma unroll
    for (int i = 0; i < 16; i++) cmax[i] = 0.f;

    #pragma unroll
    for (int mt = 0; mt < 2; mt++) {
        #pragma unroll
        for (int ih = 0; ih < 2; ih++) {
            int rl = wm + mt * 16 + ih * 8 + (lane >> 2);
            #pragma unroll
            for (int bt = 0; bt < 8; bt++) {
                int ccl = wn + bt * 8 + (lane & 3) * 2;
                int cc = col0 + ccl;
                float v0 = fmaxf(acc[mt][bt][ih * 2 + 0] + bias[cc], 0.f);
                float v1 = fmaxf(acc[mt][bt][ih * 2 + 1] + bias[cc + 1], 0.f);
                size_t idx = (size_t)(row0 + rl) * 256 + cc;
                bf16 h0, l0, h1, l1;
                split2(v0, h0, l0); split2(v1, h1, l1);
                __nv_bfloat162 hp = {h0, h1}, lp = {l0, l1};
                *(__nv_bfloat162*)(Ch + idx) = hp;
                *(__nv_bfloat162*)(Cl + idx) = lp;
                cmax[bt * 2]     = fmaxf(cmax[bt * 2], v0);
                cmax[bt * 2 + 1] = fmaxf(cmax[bt * 2 + 1], v1);
                if (rl == ra) {
                    size_t sid = (size_t)(3 * g + 2) * 256 + cc;
                    *(float2*)(seqf + sid) = make_float2(v0, v1);
                    *(__nv_bfloat162*)(seqh + sid) = hp;
                    *(__nv_bfloat162*)(seql + sid) = lp;
                }
            }
        }
    }
    #pragma unroll
    for (int i = 0; i < 16; i++) {
        float m = cmax[i];
        m = fmaxf(m, __shfl_xor_sync(0xffffffffu, m, 4));
        m = fmaxf(m, __shfl_xor_sync(0xffffffffu, m, 8));
        m = fmaxf(m, __shfl_xor_sync(0xffffffffu, m, 16));
        cmax[i] = m;
    }
    if ((lane >> 2) == 0) {
        #pragma unroll
        for (int bt = 0; bt < 8; bt++) {
            int ccl = wn + bt * 8 + lane * 2;
            smax[w & 3][ccl]     = cmax[bt * 2];
            smax[w & 3][ccl + 1] = cmax[bt * 2 + 1];
        }
    }
    __syncthreads();
    if (tid < 128) {
        int cc = col0 + tid;
        float m = fmaxf(fmaxf(smax[0][tid], smax[1][tid]),
                        fmaxf(smax[2][tid], smax[3][tid]));
        HAts[g * 256 + cc] = m;
        bf16 a, b;
        float nv = nodes[g * 256 + cc];
        if (g < GRP - 1) {
            size_t sid = (size_t)(3 * g + 1) * 256 + cc;
            seqf[sid] = m;
            split2(m, a, b); seqh[sid] = a; seql[sid] = b;
            sid = (size_t)(3 * g) * 256 + cc;
            seqf[sid] = nv;
            split2(nv, a, b); seqh[sid] = a; seql[sid] = b;
        } else {
            size_t sid = (size_t)(SEQL - 1) * 256 + cc;
            seqf[sid] = nv;
            split2(nv, a, b); seqh[sid] = a; seql[sid] = b;
        }
    }
}

// ---------------- TCN with halo: 256 threads, 8 warps of 16x32 ---------------
template<int DUAL>
__global__ __launch_bounds__(256, 2)
void tcn64(const bf16* __restrict__ Agh, const bf16* __restrict__ Agl,
           const bf16* __restrict__ Wgh, const bf16* __restrict__ Wgl,
           const bf16* __restrict__ Wdh, const bf16* __restrict__ Wdl,
           const float* __restrict__ bias, const float* __restrict__ Rf,
           float* __restrict__ Cf, bf16* __restrict__ Ch, bf16* __restrict__ Cl,
           int Mv, int N, int K, int npass, int dil, int doRelu)
{
    extern __shared__ char dyn[];
    uint32_t sbase = (smem_u32(dyn) + 1023u) & ~1023u;
    int tid = threadIdx.x, lane = tid & 31, w = tid >> 5;
    int wm = (w & 3) * 16, wn = (w >> 2) * 32;
    int row0 = blockIdx.y * 64, col0 = blockIdx.x * 64;
    int halo = (npass >= 3) ? 2 * dil : 0;
    int nrows = 64 + halo;
    uint32_t Abytes = (uint32_t)nrows * 128u;
    uint32_t stage = (Abytes + (uint32_t)npass * 8192u + 1023u) & ~1023u;
    int nch = K / KCH;

    auto load_stage = [&](int c, int s) {
        int k0 = c * KCH;
        uint32_t Ab = sbase + (uint32_t)s * stage;
        for (int idx = tid; idx < nrows * 8; idx += 256) {
            int row = idx >> 3, sub = idx & 7, half = sub >> 2, q = sub & 3;
            int ga = row0 - halo + row;
            const bf16* src = (half ? Agl : Agh)
                              + (size_t)(ga < 0 ? 0 : ga) * K + k0 + q * 8;
            CP16(Ab + SWZ(row * 128 + half * 64 + q * 16), src, ga >= 0);
        }
        for (int p = 0; p < npass; p++) {
            const bf16* Ph = (p < 3) ? Wgh + (size_t)p * N * K : Wdh;
            const bf16* Pl = (p < 3) ? Wgl + (size_t)p * N * K : Wdl;
            uint32_t Bb = Ab + Abytes + (uint32_t)p * 8192u;
            #pragma unroll
            for (int t = 0; t < 2; t++) {
                int idx = tid + t * 256;
                int row = idx >> 3, sub = idx & 7, half = sub >> 2, q = sub & 3;
                const bf16* src = (half ? Pl : Ph) + (size_t)(col0 + row) * K + k0 + q * 8;
                CP16(Bb + SWZ(row * 128 + half * 64 + q * 16), src, 1);
            }
        }
    };

    float acc[1][4][4] = {};
    float accR[1][4][4] = {};
    load_stage(0, 0); CP_COMMIT();
    if (nch > 1) { load_stage(1, 1); CP_COMMIT(); }
    for (int c = 0; c < nch; c++) {
        if (c + 1 < nch) { CP_WAIT1(); } else { CP_WAIT0(); }
        __syncthreads();
        uint32_t Ab = sbase + (uint32_t)(c & 1) * stage;
        for (int p = 0; p < npass; p++) {
            int aoff = (p < 3) ? p * dil : 2 * dil;
            uint32_t Bb = Ab + Abytes + (uint32_t)p * 8192u;
            if (DUAL && p == 3)
                compute_chunk_t<1, 4>(Ab, Bb, aoff, wm, wn, lane, accR);
            else
                compute_chunk_t<1, 4>(Ab, Bb, aoff, wm, wn, lane, acc);
        }
        __syncthreads();
        if (c + 2 < nch) { load_stage(c + 2, c & 1); CP_COMMIT(); }
    }

    #pragma unroll
    for (int ih = 0; ih < 2; ih++) {
        int rr = row0 + wm + ih * 8 + (lane >> 2);
        if (rr >= Mv) continue;
        #pragma unroll
        for (int bt = 0; bt < 4; bt++) {
            int cc = col0 + wn + bt * 8 + (lane & 3) * 2;
            size_t idx = (size_t)rr * N + cc;
            float v0 = acc[0][bt][ih * 2 + 0] + bias[cc];
            float v1 = acc[0][bt][ih * 2 + 1] + bias[cc + 1];
            if (doRelu) { v0 = fmaxf(v0, 0.f); v1 = fmaxf(v1, 0.f); }
            if (DUAL) {
                v0 = fmaxf(v0 + accR[0][bt][ih * 2 + 0], 0.f);
                v1 = fmaxf(v1 + accR[0][bt][ih * 2 + 1], 0.f);
            } else if (Rf) {
                float2 rv = *(const float2*)(Rf + idx);
                v0 = fmaxf(v0 + rv.x, 0.f);
                v1 = fmaxf(v1 + rv.y, 0.f);
            }
            if (Cf) *(float2*)(Cf + idx) = make_float2(v0, v1);
            if (Ch) {
                bf16 h0, l0, h1, l1;
                split2(v0, h0, l0); split2(v1, h1, l1);
                __nv_bfloat162 hp = {h0, h1}, lp = {l0, l1};
                *(__nv_bfloat162*)(Ch + idx) = hp;
                *(__nv_bfloat162*)(Cl + idx) = lp;
            }
        }
    }
}

static int tcn_dyn(int npass, int dil) {
    int halo = (npass >= 3) ? 2 * dil : 0;
    unsigned Abytes = (unsigned)(64 + halo) * 128u;
    unsigned stage = (Abytes + (unsigned)npass * 8192u + 1023u) & ~1023u;
    return (int)(2 * stage + 1024);
}

// ---------------- fused final: out = relu(hats@Wp1bot + GT[g]) @ Wp2 + bp2 --
#define FIN_STAGE 32768u
#define FIN_DYN   (2 * 32768 + 1024)
__global__ __launch_bounds__(256, 2)
void final_mma(const bf16* __restrict__ Hh, const bf16* __restrict__ Hl,
               const bf16* __restrict__ Bgh, const bf16* __restrict__ Bgl,
               const float* __restrict__ GT, const float* __restrict__ W2,
               const float* __restrict__ bp2, float* __restrict__ out)
{
    extern __shared__ char dyn[];
    __shared__ float sGT[512], sW2[512], sred[128][2];
    uint32_t sbase = (smem_u32(dyn) + 1023u) & ~1023u;
    int g = blockIdx.x;
    int tid = threadIdx.x, lane = tid & 31, w = tid >> 5;
    int wm = (w & 3) * 32, wn = (w >> 2) * 64;

    for (int i = tid; i < 512; i += 256) {
        sGT[i] = GT[(size_t)g * 512 + i];
        sW2[i] = W2[i];
    }

    const bf16* Ah = Hh + (size_t)g * PER * DIM;
    const bf16* Al = Hl + (size_t)g * PER * DIM;

    auto load_stage = [&](int c, int s) {
        int nt = c >> 3;
        int k0 = (c & 7) * KCH;
        uint32_t Ab = sbase + (uint32_t)s * FIN_STAGE;
        uint32_t Bb = Ab + 16384u;
        #pragma unroll
        for (int t = 0; t < 4; t++) {
            int idx = tid + t * 256;
            int row = idx >> 3, sub = idx & 7, half = sub >> 2, q = sub & 3;
            const bf16* src = (half ? Al : Ah) + (size_t)row * DIM + k0 + q * 8;
            CP16(Ab + SWZ(row * 128 + half * 64 + q * 16), src, 1);
        }
        #pragma unroll
        for (int t = 0; t < 4; t++) {
            int idx = tid + t * 256;
            int row = idx >> 3, sub = idx & 7, half = sub >> 2, q = sub & 3;
            const bf16* src = (half ? Bgl : Bgh)
                              + (size_t)(nt * 128 + row) * DIM + k0 + q * 8;
            CP16(Bb + SWZ(row * 128 + half * 64 + q * 16), src, 1);
        }
    };

    float acc[2][8][4] = {};
    float qsum[4] = {};
    const int nch = 32;
    load_stage(0, 0); CP_COMMIT();
    load_stage(1, 1); CP_COMMIT();
    for (int c = 0; c < nch; c++) {
        if (c + 1 < nch) { CP_WAIT1(); } else { CP_WAIT0(); }
        __syncthreads();
        uint32_t Ab = sbase + (uint32_t)(c & 1) * FIN_STAGE;
        compute_chunk_t<2, 8>(Ab, Ab + 16384u, 0, wm, wn, lane, acc);
        __syncthreads();
        if (c + 2 < nch) { load_stage(c + 2, c & 1); CP_COMMIT(); }
        if ((c & 7) == 7) {
            int nt = c >> 3;
            #pragma unroll
            for (int mt = 0; mt < 2; mt++) {
                #pragma unroll
                for (int bt = 0; bt < 8; bt++) {
                    #pragma unroll
                    for (int i = 0; i < 4; i++) {
                        int cc = nt * 128 + wn + bt * 8 + (lane & 3) * 2 + (i & 1);
                        float hv = fmaxf(acc[mt][bt][i] + sGT[cc], 0.f);
                        qsum[mt * 2 + (i >> 1)] += hv * sW2[cc];
                        acc[mt][bt][i] = 0.f;
                    }
                }
            }
        }
    }

    #pragma unroll
    for (int mt = 0; mt < 2; mt++) {
        #pragma unroll
        for (int ih = 0; ih < 2; ih++) {
            float v = qsum[mt * 2 + ih];
            v += __shfl_xor_sync(0xffffffffu, v, 1);
            v += __shfl_xor_sync(0xffffffffu, v, 2);
            if ((lane & 3) == 0)
                sred[wm + mt * 16 + ih * 8 + (lane >> 2)][w >> 2] = v;
        }
    }
    __syncthreads();
    if (tid < 128)
        out[(size_t)g * PER + tid] = sred[tid][0] + sred[tid][1] + bp2[0];
}

// ---------------- build state_HS = [query | hs | HAts] (hi/lo) --------------
__global__ void build_sHS(const float* __restrict__ query, const float* __restrict__ xf,
                          const float* __restrict__ HAts, bf16* __restrict__ h,
                          bf16* __restrict__ l)
{
    int g = blockIdx.x, c = threadIdx.x;
    bf16 a, b;
    split2(query[g * DIM + c], a, b);
    h[g * 768 + c] = a; l[g * 768 + c] = b;
    split2(xf[(size_t)(3 * g) * DIM + c], a, b);
    h[g * 768 + 256 + c] = a; l[g * 768 + 256 + c] = b;
    split2(HAts[g * DIM + c], a, b);
    h[g * 768 + 512 + c] = a; l[g * 768 + 512 + c] = b;
}

// ---------------- launcher --------------------------------------------------
extern "C" void kernel_launch(void* const* d_in, const int* in_sizes, int n_in,
                              void* d_out, int out_size)
{
    const float* NEs   = (const float*)d_in[0];
    const float* nodes = (const float*)d_in[1];
    const float* query = (const float*)d_in[2];
    const int*   act   = (const int*)d_in[4];
    const float* Wa    = (const float*)d_in[5];
    const float* ba    = (const float*)d_in[6];
    const float* Wc0   = (const float*)d_in[7];
    const float* bc0   = (const float*)d_in[8];
    const float* Wc1   = (const float*)d_in[9];
    const float* bc1   = (const float*)d_in[10];
    const float* Wd1   = (const float*)d_in[11];
    const float* Wc2   = (const float*)d_in[12];
    const float* bc2   = (const float*)d_in[13];
    const float* Wc3   = (const float*)d_in[14];
    const float* bc3   = (const float*)d_in[15];
    const float* Wd3   = (const float*)d_in[16];
    const float* Wp1   = (const float*)d_in[17];
    const float* bp1   = (const float*)d_in[18];
    const float* Wp2   = (const float*)d_in[19];
    const float* bp2   = (const float*)d_in[20];
    float* out = (float*)d_out;

    int tcn_max = tcn_dyn(4, 8);
    cudaFuncSetAttribute(hats_gemm, cudaFuncAttributeMaxDynamicSharedMemorySize, G128_DYN);
    cudaFuncSetAttribute(tcn64<0>,  cudaFuncAttributeMaxDynamicSharedMemorySize, tcn_max);
    cudaFuncSetAttribute(tcn64<1>,  cudaFuncAttributeMaxDynamicSharedMemorySize, tcn_max);
    cudaFuncSetAttribute(final_mma, cudaFuncAttributeMaxDynamicSharedMemorySize, FIN_DYN);

    bf16 *hh, *hl, *seqh, *seql, *x1h, *x1l, *x2h, *x2l;
    bf16 *wah, *wal, *wc0h, *wc0l, *wc1h, *wc1l, *wc2h, *wc2l, *wc3h, *wc3l;
    bf16 *wd1h, *wd1l, *wd3h, *wd3l, *wp1th, *wp1tl, *wp1bh, *wp1bl, *sHSh, *sHSl;
    float *HAts, *seqf, *x2f, *GT;
    cudaGetSymbolAddress((void**)&hh,   g_hh);    cudaGetSymbolAddress((void**)&hl,   g_hl);
    cudaGetSymbolAddress((void**)&HAts, g_HAts);
    cudaGetSymbolAddress((void**)&seqf, g_seqf);
    cudaGetSymbolAddress((void**)&seqh, g_seqh);  cudaGetSymbolAddress((void**)&seql, g_seql);
    cudaGetSymbolAddress((void**)&x1h,  g_x1h);   cudaGetSymbolAddress((void**)&x1l,  g_x1l);
    cudaGetSymbolAddress((void**)&x2f,  g_x2f);
    cudaGetSymbolAddress((void**)&x2h,  g_x2h);   cudaGetSymbolAddress((void**)&x2l,  g_x2l);
    cudaGetSymbolAddress((void**)&wah,  g_wah);   cudaGetSymbolAddress((void**)&wal,  g_wal);
    cudaGetSymbolAddress((void**)&wc0h, g_wc0h);  cudaGetSymbolAddress((void**)&wc0l, g_wc0l);
    cudaGetSymbolAddress((void**)&wc1h, g_wc1h);  cudaGetSymbolAddress((void**)&wc1l, g_wc1l);
    cudaGetSymbolAddress((void**)&wc2h, g_wc2h);  cudaGetSymbolAddress((void**)&wc2l, g_wc2l);
    cudaGetSymbolAddress((void**)&wc3h, g_wc3h);  cudaGetSymbolAddress((void**)&wc3l, g_wc3l);
    cudaGetSymbolAddress((void**)&wd1h, g_wd1h);  cudaGetSymbolAddress((void**)&wd1l, g_wd1l);
    cudaGetSymbolAddress((void**)&wd3h, g_wd3h);  cudaGetSymbolAddress((void**)&wd3l, g_wd3l);
    cudaGetSymbolAddress((void**)&wp1th, g_wp1th); cudaGetSymbolAddress((void**)&wp1tl, g_wp1tl);
    cudaGetSymbolAddress((void**)&wp1bh, g_wp1bh); cudaGetSymbolAddress((void**)&wp1bl, g_wp1bl);
    cudaGetSymbolAddress((void**)&sHSh, g_sHSh);  cudaGetSymbolAddress((void**)&sHSl, g_sHSl);
    cudaGetSymbolAddress((void**)&GT,   g_GT);

    // 0) weight prep
    split_weights<<<SPLITW_BLOCKS, 256>>>(Wa, Wc0, Wc1, Wc2, Wc3, Wd1, Wd3, Wp1,
        wah, wal, wc0h, wc0l, wc1h, wc1l, wc2h, wc2l, wc3h, wc3l,
        wd1h, wd1l, wd3h, wd3l, wp1th, wp1tl, wp1bh, wp1bl);

    // 1) hats GEMM (fp32 A direct) + fused segmax/act/state_seq
    hats_gemm<<<dim3(2, GRP), 256, G128_DYN>>>(NEs, wah, wal, ba,
        nodes, act, hh, hl, HAts, seqf, seqh, seql);

    // 2) TCN: 256 threads, 8 warps/block
    tcn64<0><<<dim3(4, 24), 256, tcn_dyn(3, 1)>>>(seqh, seql, wc0h, wc0l,
        nullptr, nullptr, bc0, seqf, nullptr, x1h, x1l, SEQL, 256, 256, 3, 1, 1);
    tcn64<1><<<dim3(8, 24), 256, tcn_dyn(4, 2)>>>(x1h, x1l, wc1h, wc1l,
        wd1h, wd1l, bc1, nullptr, x2f, x2h, x2l, SEQL, 512, 256, 4, 2, 1);
    tcn64<0><<<dim3(8, 24), 256, tcn_dyn(3, 4)>>>(x2h, x2l, wc2h, wc2l,
        nullptr, nullptr, bc2, x2f, nullptr, x1h, x1l, SEQL, 512, 512, 3, 4, 1);
    tcn64<1><<<dim3(4, 24), 256, tcn_dyn(4, 8)>>>(x1h, x1l, wc3h, wc3l,
        wd3h, wd3l, bc3, nullptr, x2f, nullptr, nullptr, SEQL, 256, 512, 4, 8, 1);

    // 3) state_HS and group term GT = sHS @ Wp1top + bp1
    build_sHS<<<GRP, DIM>>>(query, x2f, HAts, sHSh, sHSl);
    tcn64<0><<<dim3(8, 8), 256, tcn_dyn(1, 0)>>>(sHSh, sHSl, wp1th, wp1tl,
        nullptr, nullptr, bp1, nullptr, GT, nullptr, nullptr, GRP, HID, 768, 1, 0, 0);

    // 4) fused final GEMM + Wp2 reduction (128x128 tiles)
    final_mma<<<GRP, 256, FIN_DYN>>>(hh, hl, wp1bh, wp1bl, GT, Wp2, bp2, out);
}

// round 14
// speedup vs baseline: 1.6915x; 1.0581x over previous
#include <cuda_runtime.h>
#include <cuda_bf16.h>
#include <cstdint>

#define N_TOT 65536
#define GRP   512
#define PER   128
#define DIM   256
#define SEQL  1534
#define HID   512
#define KCH   32

typedef __nv_bfloat16 bf16;

// ---------------- scratch (device globals; no allocation allowed) ----------
__device__ bf16  g_hh  [N_TOT * DIM];
__device__ bf16  g_hl  [N_TOT * DIM];
__device__ float g_HAts[GRP * DIM];
__device__ float g_seqf[1536 * DIM];
__device__ bf16  g_seqh[1536 * DIM];
__device__ bf16  g_seql[1536 * DIM];
__device__ bf16  g_x1h [1536 * 512];
__device__ bf16  g_x1l [1536 * 512];
__device__ float g_x2f [1536 * 512];
__device__ bf16  g_x2h [1536 * 512];
__device__ bf16  g_x2l [1536 * 512];
__device__ bf16  g_wah [DIM * DIM];
__device__ bf16  g_wal [DIM * DIM];
__device__ bf16  g_wc0h[3 * 256 * 256];
__device__ bf16  g_wc0l[3 * 256 * 256];
__device__ bf16  g_wc1h[3 * 512 * 256];
__device__ bf16  g_wc1l[3 * 512 * 256];
__device__ bf16  g_wc2h[3 * 512 * 512];
__device__ bf16  g_wc2l[3 * 512 * 512];
__device__ bf16  g_wc3h[3 * 256 * 512];
__device__ bf16  g_wc3l[3 * 256 * 512];
__device__ bf16  g_wd1h[512 * 256];
__device__ bf16  g_wd1l[512 * 256];
__device__ bf16  g_wd3h[256 * 512];
__device__ bf16  g_wd3l[256 * 512];
__device__ bf16  g_wp1th[512 * 768];
__device__ bf16  g_wp1tl[512 * 768];
__device__ bf16  g_wp1bh[512 * 256];
__device__ bf16  g_wp1bl[512 * 256];
__device__ bf16  g_sHSh[GRP * 768];
__device__ bf16  g_sHSl[GRP * 768];
__device__ float g_GT  [GRP * 512];

// ---------------- low-level helpers -----------------------------------------
__device__ __forceinline__ uint32_t smem_u32(const void* p) {
    uint32_t a;
    asm("{ .reg .u64 t; cvta.to.shared.u64 t, %1; cvt.u32.u64 %0, t; }"
        : "=r"(a) : "l"(p));
    return a;
}
static __device__ __forceinline__ uint32_t SWZ(uint32_t off) {
    return off ^ ((off >> 3) & 0x70);
}
__device__ __forceinline__ void mma_bf16(float* c, const uint32_t* a, const uint32_t* b) {
    asm volatile(
        "mma.sync.aligned.m16n8k16.row.col.f32.bf16.bf16.f32 "
        "{%0,%1,%2,%3}, {%4,%5,%6,%7}, {%8,%9}, {%0,%1,%2,%3};\n"
        : "+f"(c[0]), "+f"(c[1]), "+f"(c[2]), "+f"(c[3])
        : "r"(a[0]), "r"(a[1]), "r"(a[2]), "r"(a[3]), "r"(b[0]), "r"(b[1]));
}
__device__ __forceinline__ void ldm_x4(uint32_t* r, uint32_t a) {
    asm volatile("ldmatrix.sync.aligned.m8n8.x4.shared.b16 {%0,%1,%2,%3}, [%4];"
        : "=r"(r[0]), "=r"(r[1]), "=r"(r[2]), "=r"(r[3]) : "r"(a));
}
#define CP16(dst, src, pred) do {                                              \
    int _sz = (pred) ? 16 : 0;                                                 \
    asm volatile("cp.async.cg.shared.global [%0], [%1], 16, %2;"               \
        :: "r"(dst), "l"(src), "r"(_sz) : "memory"); } while (0)
#define CP_COMMIT() asm volatile("cp.async.commit_group;" ::: "memory")
#define CP_WAIT1()  asm volatile("cp.async.wait_group 1;" ::: "memory")
#define CP_WAIT0()  asm volatile("cp.async.wait_group 0;" ::: "memory")

// ---------------- split helpers ---------------------------------------------
__device__ __forceinline__ void split2(float v, bf16& h, bf16& l) {
    h = __float2bfloat16(v);
    l = __float2bfloat16(v - __bfloat162float(h));
}
__device__ __forceinline__ void d_tsplit(const float* w, bf16* h, bf16* l,
                                         int K, int N, int i)
{
    if (i < K * N) {
        int k = i / N, n = i % N;
        bf16 a, b; split2(w[i], a, b);
        h[(size_t)n * K + k] = a;
        l[(size_t)n * K + k] = b;
    }
}
__device__ __forceinline__ void d_conv(const float* w, bf16* h, bf16* l,
                                       int Cout, int Cin, int i)
{
    if (i < Cout * Cin * 3) {
        int j  = i % 3;
        int ci = (i / 3) % Cin;
        int co = i / (3 * Cin);
        bf16 a, b; split2(w[i], a, b);
        size_t d = ((size_t)j * Cout + co) * Cin + ci;
        h[d] = a; l[d] = b;
    }
}
__device__ __forceinline__ void d_arr(const float* w, bf16* h, bf16* l, int n, int i)
{
    if (i < n) { bf16 a, b; split2(w[i], a, b); h[i] = a; l[i] = b; }
}

__global__ void split_weights(
    const float* Wa, const float* Wc0, const float* Wc1, const float* Wc2,
    const float* Wc3, const float* Wd1, const float* Wd3, const float* Wp1,
    bf16* wah, bf16* wal, bf16* wc0h, bf16* wc0l, bf16* wc1h, bf16* wc1l,
    bf16* wc2h, bf16* wc2l, bf16* wc3h, bf16* wc3l, bf16* wd1h, bf16* wd1l,
    bf16* wd3h, bf16* wd3l, bf16* wp1th, bf16* wp1tl, bf16* wp1bh, bf16* wp1bl)
{
    int b = blockIdx.x, t = threadIdx.x;
    if (b < 256)        { d_tsplit(Wa, wah, wal, 256, 256, b * 256 + t); return; }
    b -= 256;
    if (b < 768)        { d_conv(Wc0, wc0h, wc0l, 256, 256, b * 256 + t); return; }
    b -= 768;
    if (b < 1536)       { d_conv(Wc1, wc1h, wc1l, 512, 256, b * 256 + t); return; }
    b -= 1536;
    if (b < 3072)       { d_conv(Wc2, wc2h, wc2l, 512, 512, b * 256 + t); return; }
    b -= 3072;
    if (b < 1536)       { d_conv(Wc3, wc3h, wc3l, 256, 512, b * 256 + t); return; }
    b -= 1536;
    if (b < 512)        { d_arr(Wd1, wd1h, wd1l, 512 * 256, b * 256 + t); return; }
    b -= 512;
    if (b < 512)        { d_arr(Wd3, wd3h, wd3l, 256 * 512, b * 256 + t); return; }
    b -= 512;
    if (b < 1536)       { d_tsplit(Wp1, wp1th, wp1tl, 768, 512, b * 256 + t); return; }
    b -= 1536;
    if (b < 512)        { d_tsplit(Wp1 + 768 * 512, wp1bh, wp1bl, 256, 512, b * 256 + t); }
}
#define SPLITW_BLOCKS (256 + 768 + 1536 + 3072 + 1536 + 512 + 512 + 1536 + 512)

// ---------------- warp compute for one k32 chunk -----------------------------
// warp tile = MT*16 (m) x NBT*8 (n)
template<int MT, int NBT>
__device__ __forceinline__ void compute_chunk_t(uint32_t Ab, uint32_t Bb, int aoff,
                                                int wm, int wn, int lane,
                                                float acc[MT][NBT][4])
{
    int l7 = lane & 7;
    int b3 = (lane >> 3) & 1;
    int b4 = (lane >> 4) & 1;
    #pragma unroll
    for (int ks = 0; ks < 2; ks++) {
        int colb = ks * 32;
        uint32_t bh[NBT][2], bl[NBT][2];
        #pragma unroll
        for (int pp = 0; pp < NBT / 2; pp++) {
            int nrow = wn + pp * 16 + b4 * 8 + l7;
            uint32_t off = nrow * 128 + colb + b3 * 16;
            uint32_t rh[4], rl[4];
            ldm_x4(rh, Bb + SWZ(off));
            ldm_x4(rl, Bb + SWZ(off + 64));
            bh[pp * 2 + 0][0] = rh[0]; bh[pp * 2 + 0][1] = rh[1];
            bh[pp * 2 + 1][0] = rh[2]; bh[pp * 2 + 1][1] = rh[3];
            bl[pp * 2 + 0][0] = rl[0]; bl[pp * 2 + 0][1] = rl[1];
            bl[pp * 2 + 1][0] = rl[2]; bl[pp * 2 + 1][1] = rl[3];
        }
        #pragma unroll
        for (int mt = 0; mt < MT; mt++) {
            int arow = aoff + wm + mt * 16 + b3 * 8 + l7;
            uint32_t off = arow * 128 + colb + b4 * 16;
            uint32_t ah[4], al[4];
            ldm_x4(ah, Ab + SWZ(off));
            ldm_x4(al, Ab + SWZ(off + 64));
            #pragma unroll
            for (int bt = 0; bt < NBT; bt++) {
                mma_bf16(acc[mt][bt], ah, bh[bt]);
                mma_bf16(acc[mt][bt], ah, bl[bt]);
                mma_bf16(acc[mt][bt], al, bh[bt]);
            }
        }
    }
}

// ---------------- hats GEMM (fp32 A direct) + fused segmax/act/state_seq -----
// grid (2, GRP): blockIdx.y = group (128 rows), blockIdx.x = 128-col slice.
#define G128_STAGE 32768u
#define G128_DYN   (2 * 32768 + 1024)
__global__ __launch_bounds__(256, 2)
void hats_gemm(const float* __restrict__ NEs,
               const bf16* __restrict__ Wgh, const bf16* __restrict__ Wgl,
               const float* __restrict__ bias,
               const float* __restrict__ nodes, const int* __restrict__ act,
               bf16* __restrict__ Ch, bf16* __restrict__ Cl,
               float* __restrict__ HAts, float* __restrict__ seqf,
               bf16* __restrict__ seqh, bf16* __restrict__ seql)
{
    extern __shared__ char dyn[];
    __shared__ float smax[4][128];
    uint32_t sbase = (smem_u32(dyn) + 1023u) & ~1023u;
    int tid = threadIdx.x, lane = tid & 31, w = tid >> 5;
    int wm = (w & 3) * 32, wn = (w >> 2) * 64;
    int g = blockIdx.y;
    int row0 = g * 128, col0 = blockIdx.x * 128;
    const int nch = 8;   // K = 256

    auto ldsts_A = [&](int c, int s) {
        int k0 = c * KCH;
        uint32_t Ab = sbase + (uint32_t)s * G128_STAGE;
        #pragma unroll
        for (int t = 0; t < 4; t++) {
            int idx = tid + t * 256;
            int row = idx >> 3, seg = idx & 7;
            float4 f = *(const float4*)(NEs + (size_t)(row0 + row) * 256 + k0 + seg * 4);
            bf16 h0, l0, h1, l1, h2, l2, h3, l3;
            split2(f.x, h0, l0); split2(f.y, h1, l1);
            split2(f.z, h2, l2); split2(f.w, h3, l3);
            __nv_bfloat162 hp0 = {h0, h1}, hp1 = {h2, h3};
            __nv_bfloat162 lp0 = {l0, l1}, lp1 = {l2, l3};
            uint32_t ho = SWZ((uint32_t)(row * 128 + seg * 8));
            uint32_t lo = SWZ((uint32_t)(row * 128 + 64 + seg * 8));
            asm volatile("st.shared.v2.b32 [%0], {%1,%2};" :: "r"(Ab + ho),
                "r"(*(uint32_t*)&hp0), "r"(*(uint32_t*)&hp1) : "memory");
            asm volatile("st.shared.v2.b32 [%0], {%1,%2};" :: "r"(Ab + lo),
                "r"(*(uint32_t*)&lp0), "r"(*(uint32_t*)&lp1) : "memory");
        }
    };
    auto load_B = [&](int c, int s) {
        int k0 = c * KCH;
        uint32_t Bb = sbase + (uint32_t)s * G128_STAGE + 16384u;
        #pragma unroll
        for (int t = 0; t < 4; t++) {
            int idx = tid + t * 256;
            int row = idx >> 3, sub = idx & 7, half = sub >> 2, q = sub & 3;
            const bf16* src = (half ? Wgl : Wgh) + (size_t)(col0 + row) * 256 + k0 + q * 8;
            CP16(Bb + SWZ(row * 128 + half * 64 + q * 16), src, 1);
        }
    };

    float acc[2][8][4] = {};
    load_B(0, 0); CP_COMMIT();
    load_B(1, 1); CP_COMMIT();
    ldsts_A(0, 0);
    for (int c = 0; c < nch; c++) {
        if (c + 1 < nch) { CP_WAIT1(); } else { CP_WAIT0(); }
        __syncthreads();
        if (c + 1 < nch) ldsts_A(c + 1, (c + 1) & 1);
        uint32_t Ab = sbase + (uint32_t)(c & 1) * G128_STAGE;
        compute_chunk_t<2, 8>(Ab, Ab + 16384u, 0, wm, wn, lane, acc);
        __syncthreads();
        if (c + 2 < nch) { load_B(c + 2, c & 1); CP_COMMIT(); }
    }

    int ra = (g < GRP - 1) ? act[g] : -1;
    float cmax[16];
    #pragma unroll
    for (int i = 0; i < 16; i++) cmax[i] = 0.f;

    #pragma unroll
    for (int mt = 0; mt < 2; mt++) {
        #pragma unroll
        for (int ih = 0; ih < 2; ih++) {
            int rl = wm + mt * 16 + ih * 8 + (lane >> 2);
            #pragma unroll
            for (int bt = 0; bt < 8; bt++) {
                int ccl = wn + bt * 8 + (lane & 3) * 2;
                int cc = col0 + ccl;
                float v0 = fmaxf(acc[mt][bt][ih * 2 + 0] + bias[cc], 0.f);
                float v1 = fmaxf(acc[mt][bt][ih * 2 + 1] + bias[cc + 1], 0.f);
                size_t idx = (size_t)(row0 + rl) * 256 + cc;
                bf16 h0, l0, h1, l1;
                split2(v0, h0, l0); split2(v1, h1, l1);
                __nv_bfloat162 hp = {h0, h1}, lp = {l0, l1};
                *(__nv_bfloat162*)(Ch + idx) = hp;
                *(__nv_bfloat162*)(Cl + idx) = lp;
                cmax[bt * 2]     = fmaxf(cmax[bt * 2], v0);
                cmax[bt * 2 + 1] = fmaxf(cmax[bt * 2 + 1], v1);
                if (rl == ra) {
                    size_t sid = (size_t)(3 * g + 2) * 256 + cc;
                    *(float2*)(seqf + sid) = make_float2(v0, v1);
                    *(__nv_bfloat162*)(seqh + sid) = hp;
                    *(__nv_bfloat162*)(seql + sid) = lp;
                }
            }
        }
    }
    #pragma unroll
    for (int i = 0; i < 16; i++) {
        float m = cmax[i];
        m = fmaxf(m, __shfl_xor_sync(0xffffffffu, m, 4));
        m = fmaxf(m, __shfl_xor_sync(0xffffffffu, m, 8));
        m = fmaxf(m, __shfl_xor_sync(0xffffffffu, m, 16));
        cmax[i] = m;
    }
    if ((lane >> 2) == 0) {
        #pragma unroll
        for (int bt = 0; bt < 8; bt++) {
            int ccl = wn + bt * 8 + lane * 2;
            smax[w & 3][ccl]     = cmax[bt * 2];
            smax[w & 3][ccl + 1] = cmax[bt * 2 + 1];
        }
    }
    __syncthreads();
    if (tid < 128) {
        int cc = col0 + tid;
        float m = fmaxf(fmaxf(smax[0][tid], smax[1][tid]),
                        fmaxf(smax[2][tid], smax[3][tid]));
        HAts[g * 256 + cc] = m;
        bf16 a, b;
        float nv = nodes[g * 256 + cc];
        if (g < GRP - 1) {
            size_t sid = (size_t)(3 * g + 1) * 256 + cc;
            seqf[sid] = m;
            split2(m, a, b); seqh[sid] = a; seql[sid] = b;
            sid = (size_t)(3 * g) * 256 + cc;
            seqf[sid] = nv;
            split2(nv, a, b); seqh[sid] = a; seql[sid] = b;
        } else {
            size_t sid = (size_t)(SEQL - 1) * 256 + cc;
            seqf[sid] = nv;
            split2(nv, a, b); seqh[sid] = a; seql[sid] = b;
        }
    }
}

// ---------------- TCN with halo: fully templated for static scheduling ------
// 256 threads, 8 warps of 16x32.  NPASS/DIL/KV compile-time.
template<int DUAL, int NPASS, int DIL, int KV>
__global__ __launch_bounds__(256, 2)
void tcn64(const bf16* __restrict__ Agh, const bf16* __restrict__ Agl,
           const bf16* __restrict__ Wgh, const bf16* __restrict__ Wgl,
           const bf16* __restrict__ Wdh, const bf16* __restrict__ Wdl,
           const float* __restrict__ bias, const float* __restrict__ Rf,
           float* __restrict__ Cf, bf16* __restrict__ Ch, bf16* __restrict__ Cl,
           int Mv, int N, int doRelu)
{
    constexpr int HALO   = (NPASS >= 3) ? 2 * DIL : 0;
    constexpr int NROWS  = 64 + HALO;
    constexpr uint32_t ABYTES = (uint32_t)NROWS * 128u;
    constexpr uint32_t STAGE  = (ABYTES + (uint32_t)NPASS * 8192u + 1023u) & ~1023u;
    constexpr int NCH = KV / KCH;

    extern __shared__ char dyn[];
    uint32_t sbase = (smem_u32(dyn) + 1023u) & ~1023u;
    int tid = threadIdx.x, lane = tid & 31, w = tid >> 5;
    int wm = (w & 3) * 16, wn = (w >> 2) * 32;
    int row0 = blockIdx.y * 64, col0 = blockIdx.x * 64;

    auto load_stage = [&](int c, int s) {
        int k0 = c * KCH;
        uint32_t Ab = sbase + (uint32_t)s * STAGE;
        #pragma unroll
        for (int t = 0; t < (NROWS * 8 + 255) / 256; t++) {
            int idx = tid + t * 256;
            if (idx < NROWS * 8) {
                int row = idx >> 3, sub = idx & 7, half = sub >> 2, q = sub & 3;
                int ga = row0 - HALO + row;
                const bf16* src = (half ? Agl : Agh)
                                  + (size_t)(ga < 0 ? 0 : ga) * KV + k0 + q * 8;
                CP16(Ab + SWZ(row * 128 + half * 64 + q * 16), src, ga >= 0);
            }
        }
        #pragma unroll
        for (int p = 0; p < NPASS; p++) {
            const bf16* Ph = (p < 3) ? Wgh + (size_t)p * N * KV : Wdh;
            const bf16* Pl = (p < 3) ? Wgl + (size_t)p * N * KV : Wdl;
            uint32_t Bb = Ab + ABYTES + (uint32_t)p * 8192u;
            #pragma unroll
            for (int t = 0; t < 2; t++) {
                int idx = tid + t * 256;
                int row = idx >> 3, sub = idx & 7, half = sub >> 2, q = sub & 3;
                const bf16* src = (half ? Pl : Ph) + (size_t)(col0 + row) * KV + k0 + q * 8;
                CP16(Bb + SWZ(row * 128 + half * 64 + q * 16), src, 1);
            }
        }
    };

    float acc[1][4][4] = {};
    float accR[1][4][4] = {};
    load_stage(0, 0); CP_COMMIT();
    if (NCH > 1) { load_stage(1, 1); CP_COMMIT(); }
    #pragma unroll
    for (int c = 0; c < NCH; c++) {
        if (c + 1 < NCH) { CP_WAIT1(); } else { CP_WAIT0(); }
        __syncthreads();
        uint32_t Ab = sbase + (uint32_t)(c & 1) * STAGE;
        #pragma unroll
        for (int p = 0; p < NPASS; p++) {
            constexpr int d2 = 2 * DIL;
            int aoff = (p < 3) ? p * DIL : d2;
            uint32_t Bb = Ab + ABYTES + (uint32_t)p * 8192u;
            if (DUAL && p == 3)
                compute_chunk_t<1, 4>(Ab, Bb, aoff, wm, wn, lane, accR);
            else
                compute_chunk_t<1, 4>(Ab, Bb, aoff, wm, wn, lane, acc);
        }
        __syncthreads();
        if (c + 2 < NCH) { load_stage(c + 2, c & 1); CP_COMMIT(); }
    }

    #pragma unroll
    for (int ih = 0; ih < 2; ih++) {
        int rr = row0 + wm + ih * 8 + (lane >> 2);
        if (rr >= Mv) continue;
        #pragma unroll
        for (int bt = 0; bt < 4; bt++) {
            int cc = col0 + wn + bt * 8 + (lane & 3) * 2;
            size_t idx = (size_t)rr * N + cc;
            float v0 = acc[0][bt][ih * 2 + 0] + bias[cc];
            float v1 = acc[0][bt][ih * 2 + 1] + bias[cc + 1];
            if (doRelu) { v0 = fmaxf(v0, 0.f); v1 = fmaxf(v1, 0.f); }
            if (DUAL) {
                v0 = fmaxf(v0 + accR[0][bt][ih * 2 + 0], 0.f);
                v1 = fmaxf(v1 + accR[0][bt][ih * 2 + 1], 0.f);
            } else if (Rf) {
                float2 rv = *(const float2*)(Rf + idx);
                v0 = fmaxf(v0 + rv.x, 0.f);
                v1 = fmaxf(v1 + rv.y, 0.f);
            }
            if (Cf) *(float2*)(Cf + idx) = make_float2(v0, v1);
            if (Ch) {
                bf16 h0, l0, h1, l1;
                split2(v0, h0, l0); split2(v1, h1, l1);
                __nv_bfloat162 hp = {h0, h1}, lp = {l0, l1};
                *(__nv_bfloat162*)(Ch + idx) = hp;
                *(__nv_bfloat162*)(Cl + idx) = lp;
            }
        }
    }
}

template<int NPASS, int DIL>
static constexpr int tcn_dyn() {
    constexpr int halo = (NPASS >= 3) ? 2 * DIL : 0;
    constexpr unsigned Abytes = (unsigned)(64 + halo) * 128u;
    constexpr unsigned stage = (Abytes + (unsigned)NPASS * 8192u + 1023u) & ~1023u;
    return (int)(2 * stage + 1024);
}

// ---------------- fused final: out = relu(hats@Wp1bot + GT[g]) @ Wp2 + bp2 --
#define FIN_STAGE 32768u
#define FIN_DYN   (2 * 32768 + 1024)
__global__ __launch_bounds__(256, 2)
void final_mma(const bf16* __restrict__ Hh, const bf16* __restrict__ Hl,
               const bf16* __restrict__ Bgh, const bf16* __restrict__ Bgl,
               const float* __restrict__ GT, const float* __restrict__ W2,
               const float* __restrict__ bp2, float* __restrict__ out)
{
    extern __shared__ char dyn[];
    __shared__ float sGT[512], sW2[512], sred[128][2];
    uint32_t sbase = (smem_u32(dyn) + 1023u) & ~1023u;
    int g = blockIdx.x;
    int tid = threadIdx.x, lane = tid & 31, w = tid >> 5;
    int wm = (w & 3) * 32, wn = (w >> 2) * 64;

    for (int i = tid; i < 512; i += 256) {
        sGT[i] = GT[(size_t)g * 512 + i];
        sW2[i] = W2[i];
    }

    const bf16* Ah = Hh + (size_t)g * PER * DIM;
    const bf16* Al = Hl + (size_t)g * PER * DIM;

    auto load_stage = [&](int c, int s) {
        int nt = c >> 3;
        int k0 = (c & 7) * KCH;
        uint32_t Ab = sbase + (uint32_t)s * FIN_STAGE;
        uint32_t Bb = Ab + 16384u;
        #pragma unroll
        for (int t = 0; t < 4; t++) {
            int idx = tid + t * 256;
            int row = idx >> 3, sub = idx & 7, half = sub >> 2, q = sub & 3;
            const bf16* src = (half ? Al : Ah) + (size_t)row * DIM + k0 + q * 8;
            CP16(Ab + SWZ(row * 128 + half * 64 + q * 16), src, 1);
        }
        #pragma unroll
        for (int t = 0; t < 4; t++) {
            int idx = tid + t * 256;
            int row = idx >> 3, sub = idx & 7, half = sub >> 2, q = sub & 3;
            const bf16* src = (half ? Bgl : Bgh)
                              + (size_t)(nt * 128 + row) * DIM + k0 + q * 8;
            CP16(Bb + SWZ(row * 128 + half * 64 + q * 16), src, 1);
        }
    };

    float acc[2][8][4] = {};
    float qsum[4] = {};
    const int nch = 32;
    load_stage(0, 0); CP_COMMIT();
    load_stage(1, 1); CP_COMMIT();
    for (int c = 0; c < nch; c++) {
        if (c + 1 < nch) { CP_WAIT1(); } else { CP_WAIT0(); }
        __syncthreads();
        uint32_t Ab = sbase + (uint32_t)(c & 1) * FIN_STAGE;
        compute_chunk_t<2, 8>(Ab, Ab + 16384u, 0, wm, wn, lane, acc);
        __syncthreads();
        if (c + 2 < nch) { load_stage(c + 2, c & 1); CP_COMMIT(); }
        if ((c & 7) == 7) {
            int nt = c >> 3;
            #pragma unroll
            for (int mt = 0; mt < 2; mt++) {
                #pragma unroll
                for (int bt = 0; bt < 8; bt++) {
                    #pragma unroll
                    for (int i = 0; i < 4; i++) {
                        int cc = nt * 128 + wn + bt * 8 + (lane & 3) * 2 + (i & 1);
                        float hv = fmaxf(acc[mt][bt][i] + sGT[cc], 0.f);
                        qsum[mt * 2 + (i >> 1)] += hv * sW2[cc];
                        acc[mt][bt][i] = 0.f;
                    }
                }
            }
        }
    }

    #pragma unroll
    for (int mt = 0; mt < 2; mt++) {
        #pragma unroll
        for (int ih = 0; ih < 2; ih++) {
            float v = qsum[mt * 2 + ih];
            v += __shfl_xor_sync(0xffffffffu, v, 1);
            v += __shfl_xor_sync(0xffffffffu, v, 2);
            if ((lane & 3) == 0)
                sred[wm + mt * 16 + ih * 8 + (lane >> 2)][w >> 2] = v;
        }
    }
    __syncthreads();
    if (tid < 128)
        out[(size_t)g * PER + tid] = sred[tid][0] + sred[tid][1] + bp2[0];
}

// ---------------- build state_HS = [query | hs | HAts] (hi/lo) --------------
__global__ void build_sHS(const float* __restrict__ query, const float* __restrict__ xf,
                          const float* __restrict__ HAts, bf16* __restrict__ h,
                          bf16* __restrict__ l)
{
    int g = blockIdx.x, c = threadIdx.x;
    bf16 a, b;
    split2(query[g * DIM + c], a, b);
    h[g * 768 + c] = a; l[g * 768 + c] = b;
    split2(xf[(size_t)(3 * g) * DIM + c], a, b);
    h[g * 768 + 256 + c] = a; l[g * 768 + 256 + c] = b;
    split2(HAts[g * DIM + c], a, b);
    h[g * 768 + 512 + c] = a; l[g * 768 + 512 + c] = b;
}

// ---------------- launcher --------------------------------------------------
extern "C" void kernel_launch(void* const* d_in, const int* in_sizes, int n_in,
                              void* d_out, int out_size)
{
    const float* NEs   = (const float*)d_in[0];
    const float* nodes = (const float*)d_in[1];
    const float* query = (const float*)d_in[2];
    const int*   act   = (const int*)d_in[4];
    const float* Wa    = (const float*)d_in[5];
    const float* ba    = (const float*)d_in[6];
    const float* Wc0   = (const float*)d_in[7];
    const float* bc0   = (const float*)d_in[8];
    const float* Wc1   = (const float*)d_in[9];
    const float* bc1   = (const float*)d_in[10];
    const float* Wd1   = (const float*)d_in[11];
    const float* Wc2   = (const float*)d_in[12];
    const float* bc2   = (const float*)d_in[13];
    const float* Wc3   = (const float*)d_in[14];
    const float* bc3   = (const float*)d_in[15];
    const float* Wd3   = (const float*)d_in[16];
    const float* Wp1   = (const float*)d_in[17];
    const float* bp1   = (const float*)d_in[18];
    const float* Wp2   = (const float*)d_in[19];
    const float* bp2   = (const float*)d_in[20];
    float* out = (float*)d_out;

    cudaFuncSetAttribute(hats_gemm, cudaFuncAttributeMaxDynamicSharedMemorySize, G128_DYN);
    cudaFuncSetAttribute((const void*)tcn64<0, 3, 1, 256>,
        cudaFuncAttributeMaxDynamicSharedMemorySize, tcn_dyn<3, 1>());
    cudaFuncSetAttribute((const void*)tcn64<1, 4, 2, 256>,
        cudaFuncAttributeMaxDynamicSharedMemorySize, tcn_dyn<4, 2>());
    cudaFuncSetAttribute((const void*)tcn64<0, 3, 4, 512>,
        cudaFuncAttributeMaxDynamicSharedMemorySize, tcn_dyn<3, 4>());
    cudaFuncSetAttribute((const void*)tcn64<1, 4, 8, 512>,
        cudaFuncAttributeMaxDynamicSharedMemorySize, tcn_dyn<4, 8>());
    cudaFuncSetAttribute((const void*)tcn64<0, 1, 0, 768>,
        cudaFuncAttributeMaxDynamicSharedMemorySize, tcn_dyn<1, 0>());
    cudaFuncSetAttribute(final_mma, cudaFuncAttributeMaxDynamicSharedMemorySize, FIN_DYN);

    bf16 *hh, *hl, *seqh, *seql, *x1h, *x1l, *x2h, *x2l;
    bf16 *wah, *wal, *wc0h, *wc0l, *wc1h, *wc1l, *wc2h, *wc2l, *wc3h, *wc3l;
    bf16 *wd1h, *wd1l, *wd3h, *wd3l, *wp1th, *wp1tl, *wp1bh, *wp1bl, *sHSh, *sHSl;
    float *HAts, *seqf, *x2f, *GT;
    cudaGetSymbolAddress((void**)&hh,   g_hh);    cudaGetSymbolAddress((void**)&hl,   g_hl);
    cudaGetSymbolAddress((void**)&HAts, g_HAts);
    cudaGetSymbolAddress((void**)&seqf, g_seqf);
    cudaGetSymbolAddress((void**)&seqh, g_seqh);  cudaGetSymbolAddress((void**)&seql, g_seql);
    cudaGetSymbolAddress((void**)&x1h,  g_x1h);   cudaGetSymbolAddress((void**)&x1l,  g_x1l);
    cudaGetSymbolAddress((void**)&x2f,  g_x2f);
    cudaGetSymbolAddress((void**)&x2h,  g_x2h);   cudaGetSymbolAddress((void**)&x2l,  g_x2l);
    cudaGetSymbolAddress((void**)&wah,  g_wah);   cudaGetSymbolAddress((void**)&wal,  g_wal);
    cudaGetSymbolAddress((void**)&wc0h, g_wc0h);  cudaGetSymbolAddress((void**)&wc0l, g_wc0l);
    cudaGetSymbolAddress((void**)&wc1h, g_wc1h);  cudaGetSymbolAddress((void**)&wc1l, g_wc1l);
    cudaGetSymbolAddress((void**)&wc2h, g_wc2h);  cudaGetSymbolAddress((void**)&wc2l, g_wc2l);
    cudaGetSymbolAddress((void**)&wc3h, g_wc3h);  cudaGetSymbolAddress((void**)&wc3l, g_wc3l);
    cudaGetSymbolAddress((void**)&wd1h, g_wd1h);  cudaGetSymbolAddress((void**)&wd1l, g_wd1l);
    cudaGetSymbolAddress((void**)&wd3h, g_wd3h);  cudaGetSymbolAddress((void**)&wd3l, g_wd3l);
    cudaGetSymbolAddress((void**)&wp1th, g_wp1th); cudaGetSymbolAddress((void**)&wp1tl, g_wp1tl);
    cudaGetSymbolAddress((void**)&wp1bh, g_wp1bh); cudaGetSymbolAddress((void**)&wp1bl, g_wp1bl);
    cudaGetSymbolAddress((void**)&sHSh, g_sHSh);  cudaGetSymbolAddress((void**)&sHSl, g_sHSl);
    cudaGetSymbolAddress((void**)&GT,   g_GT);

    // 0) weight prep
    split_weights<<<SPLITW_BLOCKS, 256>>>(Wa, Wc0, Wc1, Wc2, Wc3, Wd1, Wd3, Wp1,
        wah, wal, wc0h, wc0l, wc1h, wc1l, wc2h, wc2l, wc3h, wc3l,
        wd1h, wd1l, wd3h, wd3l, wp1th, wp1tl, wp1bh, wp1bl);

    // 1) hats GEMM (fp32 A direct) + fused segmax/act/state_seq
    hats_gemm<<<dim3(2, GRP), 256, G128_DYN>>>(NEs, wah, wal, ba,
        nodes, act, hh, hl, HAts, seqf, seqh, seql);

    // 2) TCN: fully templated
    tcn64<0, 3, 1, 256><<<dim3(4, 24), 256, tcn_dyn<3, 1>()>>>(seqh, seql,
        wc0h, wc0l, nullptr, nullptr, bc0, seqf, nullptr, x1h, x1l, SEQL, 256, 1);
    tcn64<1, 4, 2, 256><<<dim3(8, 24), 256, tcn_dyn<4, 2>()>>>(x1h, x1l,
        wc1h, wc1l, wd1h, wd1l, bc1, nullptr, x2f, x2h, x2l, SEQL, 512, 1);
    tcn64<0, 3, 4, 512><<<dim3(8, 24), 256, tcn_dyn<3, 4>()>>>(x2h, x2l,
        wc2h, wc2l, nullptr, nullptr, bc2, x2f, nullptr, x1h, x1l, SEQL, 512, 1);
    tcn64<1, 4, 8, 512><<<dim3(4, 24), 256, tcn_dyn<4, 8>()>>>(x1h, x1l,
        wc3h, wc3l, wd3h, wd3l, bc3, nullptr, x2f, nullptr, nullptr, SEQL, 256, 1);

    // 3) state_HS and group term GT = sHS @ Wp1top + bp1
    build_sHS<<<GRP, DIM>>>(query, x2f, HAts, sHSh, sHSl);
    tcn64<0, 1, 0, 768><<<dim3(8, 8), 256, tcn_dyn<1, 0>()>>>(sHSh, sHSl,
        wp1th, wp1tl, nullptr, nullptr, bp1, nullptr, GT, nullptr, nullptr,
        GRP, HID, 0);

    // 4) fused final GEMM + Wp2 reduction (128x128 tiles)
    final_mma<<<GRP, 256, FIN_DYN>>>(hh, hl, wp1bh, wp1bl, GT, Wp2, bp2, out);
}